// round 9
// baseline (speedup 1.0000x reference)
#include <cuda_runtime.h>
#include <cuda_bf16.h>
#include <cstdint>

#define NU 100000
#define NS 50000
#define NE 600000
#define DIN 128
#define H1 128
#define H2 64

// ---------------- scratch (device globals; no allocations allowed) ----------
__device__ float g_mean_user[NU * DIN];
__device__ float g_mean_song[NS * DIN];
__device__ float g_h_user[NU * H1];
__device__ float g_h_song[NS * H1];
__device__ int g_cnt_user[NU];
__device__ int g_cnt_song[NS];
__device__ int g_off_user[NU];
__device__ int g_off_song[NS];
__device__ int g_fin_user[NU];
__device__ int g_fin_song[NS];
__device__ int g_cur_user[NU];
__device__ int g_cur_song[NS];
__device__ int g_srt_us[NE];
__device__ int g_srt_su[NE];
__device__ int g_part[256];

// ---------------- helpers ----------------------------------------------------
__device__ __forceinline__ uint32_t smem_u32(const void* p) {
    uint32_t a;
    asm("{ .reg .u64 t; cvta.to.shared.u64 t, %1; cvt.u32.u64 %0, t; }"
        : "=r"(a) : "l"(p));
    return a;
}
__device__ __forceinline__ uint32_t sw128(uint32_t off) {
    return off ^ ((off >> 3) & 0x70);
}
__device__ __forceinline__ unsigned long long bfpack4(__nv_bfloat16 a,
                                                      __nv_bfloat16 b,
                                                      __nv_bfloat16 c,
                                                      __nv_bfloat16 d) {
    unsigned int lo = (unsigned int)__bfloat16_as_ushort(a) |
                      ((unsigned int)__bfloat16_as_ushort(b) << 16);
    unsigned int hi = (unsigned int)__bfloat16_as_ushort(c) |
                      ((unsigned int)__bfloat16_as_ushort(d) << 16);
    unsigned long long r;
    asm("mov.b64 %0, {%1, %2};" : "=l"(r) : "r"(lo), "r"(hi));
    return r;
}

__device__ __forceinline__ void ldsm_x4(uint32_t* r, uint32_t addr) {
    asm volatile(
        "ldmatrix.sync.aligned.m8n8.x4.shared.b16 {%0,%1,%2,%3}, [%4];"
        : "=r"(r[0]), "=r"(r[1]), "=r"(r[2]), "=r"(r[3]) : "r"(addr));
}
__device__ __forceinline__ void ldsm_x2(uint32_t* r, uint32_t addr) {
    asm volatile(
        "ldmatrix.sync.aligned.m8n8.x2.shared.b16 {%0,%1}, [%2];"
        : "=r"(r[0]), "=r"(r[1]) : "r"(addr));
}
__device__ __forceinline__ void mma16816(float* d, const uint32_t* a,
                                         const uint32_t* b) {
    asm volatile(
        "mma.sync.aligned.m16n8k16.row.col.f32.bf16.bf16.f32 "
        "{%0,%1,%2,%3}, {%4,%5,%6,%7}, {%8,%9}, {%0,%1,%2,%3};"
        : "+f"(d[0]), "+f"(d[1]), "+f"(d[2]), "+f"(d[3])
        : "r"(a[0]), "r"(a[1]), "r"(a[2]), "r"(a[3]), "r"(b[0]), "r"(b[1]));
}

// ---------------- CSR build (unchanged, proven) ------------------------------
__global__ void zero_int2(int* a, int na, int* b, int nb) {
    int i = blockIdx.x * blockDim.x + threadIdx.x;
    if (i < na) a[i] = 0;
    if (i < nb) b[i] = 0;
}

__global__ void count_kernel(const int* __restrict__ us_dst,
                             const int* __restrict__ su_dst,
                             int* __restrict__ cnt_song,
                             int* __restrict__ cnt_user, int n) {
    int i = blockIdx.x * blockDim.x + threadIdx.x;
    if (i < n) {
        atomicAdd(&cnt_song[us_dst[i]], 1);
        atomicAdd(&cnt_user[su_dst[i]], 1);
    }
}

__global__ void scan_block_dual(const int* __restrict__ cs, int* __restrict__ os,
                                int ns, const int* __restrict__ cu,
                                int* __restrict__ ou, int nu,
                                int* __restrict__ partials, int nbs) {
    __shared__ int s[1024];
    int b = blockIdx.x;
    const int* in;
    int* out;
    int n, lb;
    if (b < nbs) { in = cs; out = os; n = ns; lb = b; }
    else { in = cu; out = ou; n = nu; lb = b - nbs; }
    int gid = lb * 1024 + threadIdx.x;
    s[threadIdx.x] = (gid < n) ? in[gid] : 0;
    __syncthreads();
#pragma unroll
    for (int d = 1; d < 1024; d <<= 1) {
        int t = (threadIdx.x >= d) ? s[threadIdx.x - d] : 0;
        __syncthreads();
        s[threadIdx.x] += t;
        __syncthreads();
    }
    if (gid < n) out[gid] = s[threadIdx.x];
    if (threadIdx.x == 1023) partials[b] = s[1023];
}

__global__ void scan_partials_dual(int* p, int na, int nb) {
    __shared__ int s[128];
    int t = threadIdx.x;
    s[t] = (t < na) ? p[t] : 0;
    __syncthreads();
#pragma unroll
    for (int d = 1; d < 128; d <<= 1) {
        int v = (t >= d) ? s[t - d] : 0;
        __syncthreads();
        s[t] += v;
        __syncthreads();
    }
    if (t < na) p[t] = s[t];
    __syncthreads();
    s[t] = (t < nb) ? p[na + t] : 0;
    __syncthreads();
#pragma unroll
    for (int d = 1; d < 128; d <<= 1) {
        int v = (t >= d) ? s[t - d] : 0;
        __syncthreads();
        s[t] += v;
        __syncthreads();
    }
    if (t < nb) p[na + t] = s[t];
}

__global__ void scan_finish_dual(const int* __restrict__ rs, int* __restrict__ fs,
                                 int* __restrict__ curs, int ns,
                                 const int* __restrict__ ru, int* __restrict__ fu,
                                 int* __restrict__ curu, int nu,
                                 const int* __restrict__ partials, int nbs) {
    int i = blockIdx.x * blockDim.x + threadIdx.x;
    if (i < ns) {
        int b = i >> 10;
        fs[i] = rs[i] + ((b > 0) ? partials[b - 1] : 0);
        int c = 0;
        if (i > 0) {
            int j = i - 1, bj = j >> 10;
            c = rs[j] + ((bj > 0) ? partials[bj - 1] : 0);
        }
        curs[i] = c;
    }
    int u = i - ns;
    if (u >= 0 && u < nu) {
        int b = u >> 10;
        fu[u] = ru[u] + ((b > 0) ? partials[nbs + b - 1] : 0);
        int c = 0;
        if (u > 0) {
            int j = u - 1, bj = j >> 10;
            c = ru[j] + ((bj > 0) ? partials[nbs + bj - 1] : 0);
        }
        curu[u] = c;
    }
}

__global__ void bin_dual(const int* __restrict__ us_src,
                         const int* __restrict__ us_dst,
                         const int* __restrict__ su_src,
                         const int* __restrict__ su_dst,
                         int* __restrict__ cur_song, int* __restrict__ cur_user,
                         int* __restrict__ srt_us, int* __restrict__ srt_su,
                         int n) {
    int i = blockIdx.x * blockDim.x + threadIdx.x;
    if (i < n) {
        int p0 = atomicAdd(&cur_song[us_dst[i]], 1);
        srt_us[p0] = us_src[i];
        int p1 = atomicAdd(&cur_user[su_dst[i]], 1);
        srt_su[p1] = su_src[i];
    }
}

// ---------------- gather-mean (unchanged, proven) ----------------------------
__global__ void gather_dual(const float* __restrict__ featA,
                            const int* __restrict__ srtA,
                            const int* __restrict__ offA,
                            float* __restrict__ meanA, int nA,
                            const float* __restrict__ featB,
                            const int* __restrict__ srtB,
                            const int* __restrict__ offB,
                            float* __restrict__ meanB, int nB) {
    int g = blockIdx.x * 8 + (threadIdx.x >> 5);
    const float* feat;
    const int* srt;
    const int* off;
    float* mean;
    int d;
    if (g < nA) {
        feat = featA; srt = srtA; off = offA; mean = meanA; d = g;
    } else {
        d = g - nA;
        if (d >= nB) return;
        feat = featB; srt = srtB; off = offB; mean = meanB;
    }
    int lane = threadIdx.x & 31;
    int start = (d > 0) ? off[d - 1] : 0;
    int end = off[d];
    float4 acc = make_float4(0.f, 0.f, 0.f, 0.f);
    int i = start;
    for (; i + 4 <= end; i += 4) {
        int s0 = srt[i], s1 = srt[i + 1], s2 = srt[i + 2], s3 = srt[i + 3];
        float4 a = *reinterpret_cast<const float4*>(feat + (size_t)s0 * DIN + lane * 4);
        float4 b = *reinterpret_cast<const float4*>(feat + (size_t)s1 * DIN + lane * 4);
        float4 c = *reinterpret_cast<const float4*>(feat + (size_t)s2 * DIN + lane * 4);
        float4 e = *reinterpret_cast<const float4*>(feat + (size_t)s3 * DIN + lane * 4);
        acc.x += (a.x + b.x) + (c.x + e.x);
        acc.y += (a.y + b.y) + (c.y + e.y);
        acc.z += (a.z + b.z) + (c.z + e.z);
        acc.w += (a.w + b.w) + (c.w + e.w);
    }
    for (; i < end; ++i) {
        int s0 = srt[i];
        float4 a = *reinterpret_cast<const float4*>(feat + (size_t)s0 * DIN + lane * 4);
        acc.x += a.x; acc.y += a.y; acc.z += a.z; acc.w += a.w;
    }
    int deg = end - start;
    float inv = 1.0f / (float)((deg > 0) ? deg : 1);
    acc.x *= inv; acc.y *= inv; acc.z *= inv; acc.w *= inv;
    *reinterpret_cast<float4*>(mean + (size_t)d * DIN + lane * 4) = acc;
}

// ---------------- bf16-split tensor-core SAGE GEMM (pipelined staging) -------
// D[128, NOUT] = Xself@Ws + Xneigh@Wn, fp32 accum, via mma.sync bf16 hi/lo
// (3 passes: hi*hi + hi*lo + lo*hi). K=128 per operand, staged in 64-chunks.
// X tile for stage s+1 is LDG-prefetched into registers before stage s's mmas.
template <int NOUT>
__global__ void __launch_bounds__(256, 2) sage_gemm_mma(
    const float* __restrict__ xdA, const float* __restrict__ mnA,
    const float* __restrict__ WsA, const float* __restrict__ WnA,
    const float* __restrict__ bA, float* __restrict__ outA, int MA, int nblkA,
    const float* __restrict__ xdB, const float* __restrict__ mnB,
    const float* __restrict__ WsB, const float* __restrict__ WnB,
    const float* __restrict__ bB, float* __restrict__ outB, int MB,
    int do_relu) {
    constexpr int BM = 128;
    constexpr int NT = NOUT / 16;        // n-tiles per warp: 8 / 4
    constexpr int A_BYTES = BM * 128;    // [128 rows][64 bf16 = 128B] = 16KB
    constexpr int B_BYTES = NOUT * 128;  // [NOUT rows][64 bf16 = 128B]
    extern __shared__ char smem[];
    char* A_HI = smem;
    char* A_LO = smem + A_BYTES;
    char* B_HI = smem + 2 * A_BYTES;
    char* B_LO = smem + 2 * A_BYTES + B_BYTES;

    // side dispatch
    const float* xdst; const float* mean; const float* Ws; const float* Wn;
    const float* bias; float* out; int M, bid;
    if ((int)blockIdx.x < nblkA) {
        xdst = xdA; mean = mnA; Ws = WsA; Wn = WnA; bias = bA; out = outA;
        M = MA; bid = blockIdx.x;
    } else {
        xdst = xdB; mean = mnB; Ws = WsB; Wn = WnB; bias = bB; out = outB;
        M = MB; bid = blockIdx.x - nblkA;
    }

    const int tid = threadIdx.x;
    const int w = tid >> 5;
    const int l = tid & 31;
    const int wm = w & 3;      // 4 warps along M (32 rows each)
    const int wn = w >> 2;     // 2 warps along N (NOUT/2 cols each)
    const int row0 = bid * BM;

    const uint32_t saAH = smem_u32(A_HI);
    const uint32_t saAL = smem_u32(A_LO);
    const uint32_t saBH = smem_u32(B_HI);
    const uint32_t saBL = smem_u32(B_LO);

    float acc[2][NT][4];
#pragma unroll
    for (int mt = 0; mt < 2; mt++)
#pragma unroll
        for (int nt = 0; nt < NT; nt++)
#pragma unroll
            for (int j = 0; j < 4; j++) acc[mt][nt][j] = 0.f;

    // staging indices
    const int ar = tid >> 1;             // A row handled by this thread
    const int ah = tid & 1;              // col half (32 fp32 each)
    constexpr int TPN = 256 / NOUT;      // threads per W column: 2 / 4
    constexpr int KB = 64 / TPN;         // k-span per thread: 32 / 16
    const int bn = tid % NOUT;
    const int bk0 = (tid / NOUT) * KB;
    const int gr = row0 + ar;
    const bool arow_ok = (gr < M);

    // ldmatrix per-lane addresses (within-chunk, before adding kt offset)
    const uint32_t a_m = (uint32_t)(l & 15);
    const uint32_t a_ch = (uint32_t)(l >> 4) * 8;
    const uint32_t b_nl = (uint32_t)(l & 7);
    const uint32_t b_ch = (uint32_t)((l >> 3) & 1) * 8;

    // A-prefetch registers: 8 x float4 = one stage's X slice for this thread
    float4 apre[8];
    {
        const float* xr = xdst + (size_t)gr * DIN + ah * 32;
#pragma unroll
        for (int i = 0; i < 8; i++)
            apre[i] = arow_ok ? *reinterpret_cast<const float4*>(xr + 4 * i)
                              : make_float4(0.f, 0.f, 0.f, 0.f);
    }

#pragma unroll
    for (int s = 0; s < 4; ++s) {
        const int op = s >> 1;
        const int ch = s & 1;
        const int kbase = ch * 64;
        const float* Wp = op ? Wn : Ws;

        __syncthreads();
        // ---- commit prefetched A regs -> bf16 hi/lo smem
        {
            const uint32_t obase = (uint32_t)(ar * 128 + ah * 64);
#pragma unroll
            for (int i = 0; i < 8; i++) {
                float4 v = apre[i];
                __nv_bfloat16 h0 = __float2bfloat16(v.x);
                __nv_bfloat16 h1 = __float2bfloat16(v.y);
                __nv_bfloat16 h2 = __float2bfloat16(v.z);
                __nv_bfloat16 h3 = __float2bfloat16(v.w);
                uint32_t o = sw128(obase + 8 * i);
                *reinterpret_cast<unsigned long long*>(A_HI + o) =
                    bfpack4(h0, h1, h2, h3);
                *reinterpret_cast<unsigned long long*>(A_LO + o) = bfpack4(
                    __float2bfloat16(v.x - __bfloat162float(h0)),
                    __float2bfloat16(v.y - __bfloat162float(h1)),
                    __float2bfloat16(v.z - __bfloat162float(h2)),
                    __float2bfloat16(v.w - __bfloat162float(h3)));
            }
        }
        // ---- stage B chunk: W[k][n] -> smem [n][64k] hi/lo (L1/L2-warm)
        {
#pragma unroll
            for (int j = 0; j < KB / 4; j++) {
                int k = bk0 + 4 * j;
                const float* wp = Wp + (size_t)(kbase + k) * NOUT + bn;
                float w0 = wp[0];
                float w1 = wp[NOUT];
                float w2 = wp[2 * NOUT];
                float w3 = wp[3 * NOUT];
                __nv_bfloat16 h0 = __float2bfloat16(w0);
                __nv_bfloat16 h1 = __float2bfloat16(w1);
                __nv_bfloat16 h2 = __float2bfloat16(w2);
                __nv_bfloat16 h3 = __float2bfloat16(w3);
                uint32_t o = sw128((uint32_t)(bn * 128 + k * 2));
                *reinterpret_cast<unsigned long long*>(B_HI + o) =
                    bfpack4(h0, h1, h2, h3);
                *reinterpret_cast<unsigned long long*>(B_LO + o) = bfpack4(
                    __float2bfloat16(w0 - __bfloat162float(h0)),
                    __float2bfloat16(w1 - __bfloat162float(h1)),
                    __float2bfloat16(w2 - __bfloat162float(h2)),
                    __float2bfloat16(w3 - __bfloat162float(h3)));
            }
        }
        __syncthreads();

        // ---- prefetch NEXT stage's A slice (overlaps the mmas below)
        if (s < 3) {
            const int nop = (s + 1) >> 1;
            const int nkb = ((s + 1) & 1) * 64;
            const float* Xn = nop ? mean : xdst;
            const float* xr = Xn + (size_t)gr * DIN + nkb + ah * 32;
#pragma unroll
            for (int i = 0; i < 8; i++)
                apre[i] = arow_ok ? *reinterpret_cast<const float4*>(xr + 4 * i)
                                  : make_float4(0.f, 0.f, 0.f, 0.f);
        }

        // ---- 3 passes x 4 k16-steps of mma
#pragma unroll
        for (int p = 0; p < 3; p++) {
            const uint32_t sa = (p == 2) ? saAL : saAH;
            const uint32_t sb = (p == 1) ? saBL : saBH;
#pragma unroll
            for (int kt = 0; kt < 4; kt++) {
                uint32_t af[2][4];
#pragma unroll
                for (int mt = 0; mt < 2; mt++) {
                    uint32_t r = (uint32_t)(wm * 32 + mt * 16) + a_m;
                    uint32_t c = (uint32_t)(kt * 16) + a_ch;
                    ldsm_x4(af[mt], sa + sw128(r * 128 + c * 2));
                }
                uint32_t bf[NT][2];
#pragma unroll
                for (int nt = 0; nt < NT; nt++) {
                    uint32_t n = (uint32_t)(wn * (NOUT / 2) + nt * 8) + b_nl;
                    uint32_t c = (uint32_t)(kt * 16) + b_ch;
                    ldsm_x2(bf[nt], sb + sw128(n * 128 + c * 2));
                }
#pragma unroll
                for (int mt = 0; mt < 2; mt++)
#pragma unroll
                    for (int nt = 0; nt < NT; nt++)
                        mma16816(acc[mt][nt], af[mt], bf[nt]);
            }
        }
    }

    // ---- epilogue: bias (+relu), direct to gmem
    const int gq = l >> 2;   // row within 16-tile: gq and gq+8
    const int tq = l & 3;    // col pair: tq*2, tq*2+1
#pragma unroll
    for (int mt = 0; mt < 2; mt++) {
        int r0g = row0 + wm * 32 + mt * 16 + gq;
#pragma unroll
        for (int nt = 0; nt < NT; nt++) {
            int col = wn * (NOUT / 2) + nt * 8 + tq * 2;
            float b0 = __ldg(&bias[col]);
            float b1 = __ldg(&bias[col + 1]);
            float d0 = acc[mt][nt][0] + b0;
            float d1 = acc[mt][nt][1] + b1;
            float d2 = acc[mt][nt][2] + b0;
            float d3 = acc[mt][nt][3] + b1;
            if (do_relu) {
                d0 = fmaxf(d0, 0.f);
                d1 = fmaxf(d1, 0.f);
                d2 = fmaxf(d2, 0.f);
                d3 = fmaxf(d3, 0.f);
            }
            if (r0g < M)
                *reinterpret_cast<float2*>(out + (size_t)r0g * NOUT + col) =
                    make_float2(d0, d1);
            if (r0g + 8 < M)
                *reinterpret_cast<float2*>(out + (size_t)(r0g + 8) * NOUT + col) =
                    make_float2(d2, d3);
        }
    }
}

// ---------------- host launch -----------------------------------------------
extern "C" void kernel_launch(void* const* d_in, const int* in_sizes, int n_in,
                              void* d_out, int out_size) {
    const float* x_user = (const float*)d_in[0];
    const float* x_song = (const float*)d_in[1];
    const int* us_src = (const int*)d_in[2];
    const int* us_dst = (const int*)d_in[3];
    const int* su_src = (const int*)d_in[4];
    const int* su_dst = (const int*)d_in[5];
    const float* W1_us_n = (const float*)d_in[6];
    const float* W1_us_s = (const float*)d_in[7];
    const float* b1_us = (const float*)d_in[8];
    const float* W1_su_n = (const float*)d_in[9];
    const float* W1_su_s = (const float*)d_in[10];
    const float* b1_su = (const float*)d_in[11];
    const float* W2_us_n = (const float*)d_in[12];
    const float* W2_us_s = (const float*)d_in[13];
    const float* b2_us = (const float*)d_in[14];
    const float* W2_su_n = (const float*)d_in[15];
    const float* W2_su_s = (const float*)d_in[16];
    const float* b2_su = (const float*)d_in[17];
    float* out = (float*)d_out;

    float *mean_user, *mean_song, *h_user, *h_song;
    int *cnt_user, *cnt_song, *off_user, *off_song, *fin_user, *fin_song;
    int *cur_user, *cur_song, *srt_us, *srt_su, *part;
    cudaGetSymbolAddress((void**)&mean_user, g_mean_user);
    cudaGetSymbolAddress((void**)&mean_song, g_mean_song);
    cudaGetSymbolAddress((void**)&h_user, g_h_user);
    cudaGetSymbolAddress((void**)&h_song, g_h_song);
    cudaGetSymbolAddress((void**)&cnt_user, g_cnt_user);
    cudaGetSymbolAddress((void**)&cnt_song, g_cnt_song);
    cudaGetSymbolAddress((void**)&off_user, g_off_user);
    cudaGetSymbolAddress((void**)&off_song, g_off_song);
    cudaGetSymbolAddress((void**)&fin_user, g_fin_user);
    cudaGetSymbolAddress((void**)&fin_song, g_fin_song);
    cudaGetSymbolAddress((void**)&cur_user, g_cur_user);
    cudaGetSymbolAddress((void**)&cur_song, g_cur_song);
    cudaGetSymbolAddress((void**)&srt_us, g_srt_us);
    cudaGetSymbolAddress((void**)&srt_su, g_srt_su);
    cudaGetSymbolAddress((void**)&part, g_part);

    const int NB_S = (NS + 1023) / 1024;  // 49
    const int NB_U = (NU + 1023) / 1024;  // 98

    const int SMEM1 = 2 * 128 * 128 + 2 * H1 * 128;  // 65536 B
    const int SMEM2 = 2 * 128 * 128 + 2 * H2 * 128;  // 49152 B
    cudaFuncSetAttribute(sage_gemm_mma<H1>,
                         cudaFuncAttributeMaxDynamicSharedMemorySize, SMEM1);
    cudaFuncSetAttribute(sage_gemm_mma<H2>,
                         cudaFuncAttributeMaxDynamicSharedMemorySize, SMEM2);

    // ---- CSR build
    zero_int2<<<(NU + 255) / 256, 256>>>(cnt_user, NU, cnt_song, NS);
    count_kernel<<<(NE + 255) / 256, 256>>>(us_dst, su_dst, cnt_song, cnt_user, NE);
    scan_block_dual<<<NB_S + NB_U, 1024>>>(cnt_song, off_song, NS, cnt_user,
                                           off_user, NU, part, NB_S);
    scan_partials_dual<<<1, 128>>>(part, NB_S, NB_U);
    scan_finish_dual<<<(NS + NU + 255) / 256, 256>>>(
        off_song, fin_song, cur_song, NS, off_user, fin_user, cur_user, NU,
        part, NB_S);
    bin_dual<<<(NE + 255) / 256, 256>>>(us_src, us_dst, su_src, su_dst, cur_song,
                                        cur_user, srt_us, srt_su, NE);

    const int naS = (NS + 127) / 128;  // 391
    const int naU = (NU + 127) / 128;  // 782

    // ---- layer 1
    gather_dual<<<(NS + NU + 7) / 8, 256>>>(x_user, srt_us, fin_song, mean_song,
                                            NS, x_song, srt_su, fin_user,
                                            mean_user, NU);
    sage_gemm_mma<H1><<<naS + naU, 256, SMEM1>>>(
        x_song, mean_song, W1_us_s, W1_us_n, b1_us, h_song, NS, naS, x_user,
        mean_user, W1_su_s, W1_su_n, b1_su, h_user, NU, 1);

    // ---- layer 2
    gather_dual<<<(NS + NU + 7) / 8, 256>>>(h_user, srt_us, fin_song, mean_song,
                                            NS, h_song, srt_su, fin_user,
                                            mean_user, NU);
    sage_gemm_mma<H2><<<naS + naU, 256, SMEM2>>>(
        h_song, mean_song, W2_us_s, W2_us_n, b2_us, out + (size_t)NU * H2, NS,
        naS, h_user, mean_user, W2_su_s, W2_su_n, b2_su, out, NU, 0);
}

// round 11
// speedup vs baseline: 1.1443x; 1.1443x over previous
#include <cuda_runtime.h>
#include <cuda_bf16.h>
#include <cstdint>

#define NU 100000
#define NS 50000
#define NE 600000
#define DIN 128
#define H1 128
#define H2 64

// ---------------- scratch (device globals; no allocations allowed) ----------
__device__ float g_mean_user[NU * DIN];
__device__ float g_mean_song[NS * DIN];
__device__ float g_h_user[NU * H1];
__device__ float g_h_song[NS * H1];
__device__ int g_cnt_user[NU];
__device__ int g_cnt_song[NS];
__device__ int g_off_user[NU];
__device__ int g_off_song[NS];
__device__ int g_fin_user[NU];
__device__ int g_fin_song[NS];
__device__ int g_cur_user[NU];
__device__ int g_cur_song[NS];
__device__ int g_srt_us[NE];
__device__ int g_srt_su[NE];
__device__ int g_part[256];
// W bf16 hi/lo swizzled tile images: 4 H1 mats (64KB each) + 4 H2 mats (32KB)
__device__ __align__(16) char g_wimg[4 * 65536 + 4 * 32768];

// ---------------- helpers ----------------------------------------------------
__device__ __forceinline__ uint32_t smem_u32(const void* p) {
    uint32_t a;
    asm("{ .reg .u64 t; cvta.to.shared.u64 t, %1; cvt.u32.u64 %0, t; }"
        : "=r"(a) : "l"(p));
    return a;
}
__host__ __device__ __forceinline__ uint32_t sw128(uint32_t off) {
    return off ^ ((off >> 3) & 0x70);
}
__device__ __forceinline__ unsigned long long bfpack4(__nv_bfloat16 a,
                                                      __nv_bfloat16 b,
                                                      __nv_bfloat16 c,
                                                      __nv_bfloat16 d) {
    unsigned int lo = (unsigned int)__bfloat16_as_ushort(a) |
                      ((unsigned int)__bfloat16_as_ushort(b) << 16);
    unsigned int hi = (unsigned int)__bfloat16_as_ushort(c) |
                      ((unsigned int)__bfloat16_as_ushort(d) << 16);
    unsigned long long r;
    asm("mov.b64 %0, {%1, %2};" : "=l"(r) : "r"(lo), "r"(hi));
    return r;
}
__device__ __forceinline__ void cp_async16(uint32_t s, const void* g) {
    asm volatile("cp.async.ca.shared.global [%0], [%1], 16;" :: "r"(s), "l"(g));
}
__device__ __forceinline__ void cp_async_commit() {
    asm volatile("cp.async.commit_group;");
}
__device__ __forceinline__ void cp_async_wait_all() {
    asm volatile("cp.async.wait_group 0;" ::: "memory");
}

__device__ __forceinline__ void ldsm_x4(uint32_t* r, uint32_t addr) {
    asm volatile(
        "ldmatrix.sync.aligned.m8n8.x4.shared.b16 {%0,%1,%2,%3}, [%4];"
        : "=r"(r[0]), "=r"(r[1]), "=r"(r[2]), "=r"(r[3]) : "r"(addr));
}
__device__ __forceinline__ void ldsm_x2(uint32_t* r, uint32_t addr) {
    asm volatile(
        "ldmatrix.sync.aligned.m8n8.x2.shared.b16 {%0,%1}, [%2];"
        : "=r"(r[0]), "=r"(r[1]) : "r"(addr));
}
__device__ __forceinline__ void mma16816(float* d, const uint32_t* a,
                                         const uint32_t* b) {
    asm volatile(
        "mma.sync.aligned.m16n8k16.row.col.f32.bf16.bf16.f32 "
        "{%0,%1,%2,%3}, {%4,%5,%6,%7}, {%8,%9}, {%0,%1,%2,%3};"
        : "+f"(d[0]), "+f"(d[1]), "+f"(d[2]), "+f"(d[3])
        : "r"(a[0]), "r"(a[1]), "r"(a[2]), "r"(a[3]), "r"(b[0]), "r"(b[1]));
}

// ---------------- W image precompute -----------------------------------------
// Image layout per matrix: [hi ch0][hi ch1][lo ch0][lo ch1], chunk = NOUT*128 B,
// within chunk: byte (n*128 + kk*2) ^ sw128, kk = k % 64 (matches GEMM B smem).
struct WPtrs {
    const float* w[8];
};
__global__ void wimg_kernel(WPtrs wp, char* img) {
    int mat = blockIdx.y;
    int N = (mat < 4) ? H1 : H2;
    int t = blockIdx.x * 256 + threadIdx.x;
    if (t >= 128 * N) return;
    int k = t / N;
    int n = t % N;
    float w = wp.w[mat][(size_t)k * N + n];
    __nv_bfloat16 hi = __float2bfloat16(w);
    __nv_bfloat16 lo = __float2bfloat16(w - __bfloat162float(hi));
    size_t base = (mat < 4) ? (size_t)mat * 65536
                            : 262144 + (size_t)(mat - 4) * 32768;
    int CHB = N * 128;
    int ch = k >> 6;
    int kk = k & 63;
    uint32_t off = (uint32_t)(ch * CHB) + sw128((uint32_t)(n * 128 + kk * 2));
    *reinterpret_cast<unsigned short*>(img + base + off) =
        __bfloat16_as_ushort(hi);
    *reinterpret_cast<unsigned short*>(img + base + 2 * CHB + off) =
        __bfloat16_as_ushort(lo);
}

// ---------------- CSR build (unchanged, proven) ------------------------------
__global__ void zero_int2(int* a, int na, int* b, int nb) {
    int i = blockIdx.x * blockDim.x + threadIdx.x;
    if (i < na) a[i] = 0;
    if (i < nb) b[i] = 0;
}

__global__ void count_kernel(const int* __restrict__ us_dst,
                             const int* __restrict__ su_dst,
                             int* __restrict__ cnt_song,
                             int* __restrict__ cnt_user, int n) {
    int i = blockIdx.x * blockDim.x + threadIdx.x;
    if (i < n) {
        atomicAdd(&cnt_song[us_dst[i]], 1);
        atomicAdd(&cnt_user[su_dst[i]], 1);
    }
}

__global__ void scan_block_dual(const int* __restrict__ cs, int* __restrict__ os,
                                int ns, const int* __restrict__ cu,
                                int* __restrict__ ou, int nu,
                                int* __restrict__ partials, int nbs) {
    __shared__ int s[1024];
    int b = blockIdx.x;
    const int* in;
    int* out;
    int n, lb;
    if (b < nbs) { in = cs; out = os; n = ns; lb = b; }
    else { in = cu; out = ou; n = nu; lb = b - nbs; }
    int gid = lb * 1024 + threadIdx.x;
    s[threadIdx.x] = (gid < n) ? in[gid] : 0;
    __syncthreads();
#pragma unroll
    for (int d = 1; d < 1024; d <<= 1) {
        int t = (threadIdx.x >= d) ? s[threadIdx.x - d] : 0;
        __syncthreads();
        s[threadIdx.x] += t;
        __syncthreads();
    }
    if (gid < n) out[gid] = s[threadIdx.x];
    if (threadIdx.x == 1023) partials[b] = s[1023];
}

__global__ void scan_partials_dual(int* p, int na, int nb) {
    __shared__ int s[128];
    int t = threadIdx.x;
    s[t] = (t < na) ? p[t] : 0;
    __syncthreads();
#pragma unroll
    for (int d = 1; d < 128; d <<= 1) {
        int v = (t >= d) ? s[t - d] : 0;
        __syncthreads();
        s[t] += v;
        __syncthreads();
    }
    if (t < na) p[t] = s[t];
    __syncthreads();
    s[t] = (t < nb) ? p[na + t] : 0;
    __syncthreads();
#pragma unroll
    for (int d = 1; d < 128; d <<= 1) {
        int v = (t >= d) ? s[t - d] : 0;
        __syncthreads();
        s[t] += v;
        __syncthreads();
    }
    if (t < nb) p[na + t] = s[t];
}

__global__ void scan_finish_dual(const int* __restrict__ rs, int* __restrict__ fs,
                                 int* __restrict__ curs, int ns,
                                 const int* __restrict__ ru, int* __restrict__ fu,
                                 int* __restrict__ curu, int nu,
                                 const int* __restrict__ partials, int nbs) {
    int i = blockIdx.x * blockDim.x + threadIdx.x;
    if (i < ns) {
        int b = i >> 10;
        fs[i] = rs[i] + ((b > 0) ? partials[b - 1] : 0);
        int c = 0;
        if (i > 0) {
            int j = i - 1, bj = j >> 10;
            c = rs[j] + ((bj > 0) ? partials[bj - 1] : 0);
        }
        curs[i] = c;
    }
    int u = i - ns;
    if (u >= 0 && u < nu) {
        int b = u >> 10;
        fu[u] = ru[u] + ((b > 0) ? partials[nbs + b - 1] : 0);
        int c = 0;
        if (u > 0) {
            int j = u - 1, bj = j >> 10;
            c = ru[j] + ((bj > 0) ? partials[nbs + bj - 1] : 0);
        }
        curu[u] = c;
    }
}

__global__ void bin_dual(const int* __restrict__ us_src,
                         const int* __restrict__ us_dst,
                         const int* __restrict__ su_src,
                         const int* __restrict__ su_dst,
                         int* __restrict__ cur_song, int* __restrict__ cur_user,
                         int* __restrict__ srt_us, int* __restrict__ srt_su,
                         int n) {
    int i = blockIdx.x * blockDim.x + threadIdx.x;
    if (i < n) {
        int p0 = atomicAdd(&cur_song[us_dst[i]], 1);
        srt_us[p0] = us_src[i];
        int p1 = atomicAdd(&cur_user[su_dst[i]], 1);
        srt_su[p1] = su_src[i];
    }
}

// ---------------- gather-mean (unchanged, proven) ----------------------------
__global__ void gather_dual(const float* __restrict__ featA,
                            const int* __restrict__ srtA,
                            const int* __restrict__ offA,
                            float* __restrict__ meanA, int nA,
                            const float* __restrict__ featB,
                            const int* __restrict__ srtB,
                            const int* __restrict__ offB,
                            float* __restrict__ meanB, int nB) {
    int g = blockIdx.x * 8 + (threadIdx.x >> 5);
    const float* feat;
    const int* srt;
    const int* off;
    float* mean;
    int d;
    if (g < nA) {
        feat = featA; srt = srtA; off = offA; mean = meanA; d = g;
    } else {
        d = g - nA;
        if (d >= nB) return;
        feat = featB; srt = srtB; off = offB; mean = meanB;
    }
    int lane = threadIdx.x & 31;
    int start = (d > 0) ? off[d - 1] : 0;
    int end = off[d];
    float4 acc = make_float4(0.f, 0.f, 0.f, 0.f);
    int i = start;
    for (; i + 4 <= end; i += 4) {
        int s0 = srt[i], s1 = srt[i + 1], s2 = srt[i + 2], s3 = srt[i + 3];
        float4 a = *reinterpret_cast<const float4*>(feat + (size_t)s0 * DIN + lane * 4);
        float4 b = *reinterpret_cast<const float4*>(feat + (size_t)s1 * DIN + lane * 4);
        float4 c = *reinterpret_cast<const float4*>(feat + (size_t)s2 * DIN + lane * 4);
        float4 e = *reinterpret_cast<const float4*>(feat + (size_t)s3 * DIN + lane * 4);
        acc.x += (a.x + b.x) + (c.x + e.x);
        acc.y += (a.y + b.y) + (c.y + e.y);
        acc.z += (a.z + b.z) + (c.z + e.z);
        acc.w += (a.w + b.w) + (c.w + e.w);
    }
    for (; i < end; ++i) {
        int s0 = srt[i];
        float4 a = *reinterpret_cast<const float4*>(feat + (size_t)s0 * DIN + lane * 4);
        acc.x += a.x; acc.y += a.y; acc.z += a.z; acc.w += a.w;
    }
    int deg = end - start;
    float inv = 1.0f / (float)((deg > 0) ? deg : 1);
    acc.x *= inv; acc.y *= inv; acc.z *= inv; acc.w *= inv;
    *reinterpret_cast<float4*>(mean + (size_t)d * DIN + lane * 4) = acc;
}

// ---------------- bf16-split tensor-core SAGE GEMM ---------------------------
// D[128, NOUT] = Xself@Ws + Xneigh@Wn, fp32 accum, via mma.sync bf16 hi/lo
// (3 passes: hi*hi + hi*lo + lo*hi). K=128 per operand, staged in 64-chunks.
// B (W) tiles come from precomputed swizzled hi/lo images via cp.async.
template <int NOUT>
__global__ void __launch_bounds__(256) sage_gemm_mma(
    const float* __restrict__ xdA, const float* __restrict__ mnA,
    const char* __restrict__ iWsA, const char* __restrict__ iWnA,
    const float* __restrict__ bA, float* __restrict__ outA, int MA, int nblkA,
    const float* __restrict__ xdB, const float* __restrict__ mnB,
    const char* __restrict__ iWsB, const char* __restrict__ iWnB,
    const float* __restrict__ bB, float* __restrict__ outB, int MB,
    int do_relu) {
    constexpr int BM = 128;
    constexpr int NT = NOUT / 16;        // n-tiles per warp: 8 / 4
    constexpr int A_BYTES = BM * 128;    // [128 rows][64 bf16 = 128B] = 16KB
    constexpr int B_BYTES = NOUT * 128;  // chunk bytes (CHB)
    constexpr int SWP = B_BYTES / (256 * 16);  // cp sweeps: 4 (H1) / 2 (H2)
    extern __shared__ char smem[];
    char* A_HI = smem;
    char* A_LO = smem + A_BYTES;
    char* B_HI = smem + 2 * A_BYTES;
    char* B_LO = smem + 2 * A_BYTES + B_BYTES;

    // side dispatch
    const float* xdst; const float* mean; const char* iWs; const char* iWn;
    const float* bias; float* out; int M, bid;
    if ((int)blockIdx.x < nblkA) {
        xdst = xdA; mean = mnA; iWs = iWsA; iWn = iWnA; bias = bA; out = outA;
        M = MA; bid = blockIdx.x;
    } else {
        xdst = xdB; mean = mnB; iWs = iWsB; iWn = iWnB; bias = bB; out = outB;
        M = MB; bid = blockIdx.x - nblkA;
    }

    const int tid = threadIdx.x;
    const int w = tid >> 5;
    const int l = tid & 31;
    const int wm = w & 3;      // 4 warps along M (32 rows each)
    const int wn = w >> 2;     // 2 warps along N (NOUT/2 cols each)
    const int row0 = bid * BM;

    const uint32_t saAH = smem_u32(A_HI);
    const uint32_t saAL = smem_u32(A_LO);
    const uint32_t saBH = smem_u32(B_HI);
    const uint32_t saBL = smem_u32(B_LO);

    float acc[2][NT][4];
#pragma unroll
    for (int mt = 0; mt < 2; mt++)
#pragma unroll
        for (int nt = 0; nt < NT; nt++)
#pragma unroll
            for (int j = 0; j < 4; j++) acc[mt][nt][j] = 0.f;

    // staging indices
    const int ar = tid >> 1;             // A row handled by this thread
    const int ah = tid & 1;              // col half (32 fp32 each)

    // ldmatrix per-lane addresses (within-chunk, before adding kt offset)
    const uint32_t a_m = (uint32_t)(l & 15);
    const uint32_t a_ch = (uint32_t)(l >> 4) * 8;
    const uint32_t b_nl = (uint32_t)(l & 7);
    const uint32_t b_ch = (uint32_t)((l >> 3) & 1) * 8;

    for (int op = 0; op < 2; ++op) {
        const float* Xp = op ? mean : xdst;
        const char* iW = op ? iWn : iWs;
        for (int ch = 0; ch < 2; ++ch) {
            const int kbase = ch * 64;
            __syncthreads();
            // ---- B tiles: async copy of precomputed swizzled hi/lo images
            {
                const char* bimg = iW + ch * B_BYTES;  // hi chunk
#pragma unroll
                for (int j = 0; j < SWP; j++) {
                    uint32_t o = (uint32_t)(tid * 16 + j * 4096);
                    cp_async16(saBH + o, bimg + o);
                    cp_async16(saBL + o, bimg + 2 * B_BYTES + o);
                }
                cp_async_commit();
            }
            // ---- stage A chunk [128 x 64] hi/lo (LDG + convert + STS)
            {
                const int gr = row0 + ar;
                const float* xr = Xp + (size_t)gr * DIN + kbase + ah * 32;
                const uint32_t obase = (uint32_t)(ar * 128 + ah * 64);
#pragma unroll
                for (int i = 0; i < 8; i++) {
                    float4 v = (gr < M)
                                   ? *reinterpret_cast<const float4*>(xr + 4 * i)
                                   : make_float4(0.f, 0.f, 0.f, 0.f);
                    __nv_bfloat16 h0 = __float2bfloat16(v.x);
                    __nv_bfloat16 h1 = __float2bfloat16(v.y);
                    __nv_bfloat16 h2 = __float2bfloat16(v.z);
                    __nv_bfloat16 h3 = __float2bfloat16(v.w);
                    uint32_t o = sw128(obase + 8 * i);
                    *reinterpret_cast<unsigned long long*>(A_HI + o) =
                        bfpack4(h0, h1, h2, h3);
                    *reinterpret_cast<unsigned long long*>(A_LO + o) = bfpack4(
                        __float2bfloat16(v.x - __bfloat162float(h0)),
                        __float2bfloat16(v.y - __bfloat162float(h1)),
                        __float2bfloat16(v.z - __bfloat162float(h2)),
                        __float2bfloat16(v.w - __bfloat162float(h3)));
                }
            }
            cp_async_wait_all();
            __syncthreads();

            // ---- 3 passes x 4 k16-steps of mma
#pragma unroll
            for (int p = 0; p < 3; p++) {
                const uint32_t sa = (p == 2) ? saAL : saAH;
                const uint32_t sb = (p == 1) ? saBL : saBH;
#pragma unroll
                for (int kt = 0; kt < 4; kt++) {
                    uint32_t af[2][4];
#pragma unroll
                    for (int mt = 0; mt < 2; mt++) {
                        uint32_t r = (uint32_t)(wm * 32 + mt * 16) + a_m;
                        uint32_t c = (uint32_t)(kt * 16) + a_ch;
                        ldsm_x4(af[mt], sa + sw128(r * 128 + c * 2));
                    }
                    uint32_t bf[NT][2];
#pragma unroll
                    for (int nt = 0; nt < NT; nt++) {
                        uint32_t n = (uint32_t)(wn * (NOUT / 2) + nt * 8) + b_nl;
                        uint32_t c = (uint32_t)(kt * 16) + b_ch;
                        ldsm_x2(bf[nt], sb + sw128(n * 128 + c * 2));
                    }
#pragma unroll
                    for (int mt = 0; mt < 2; mt++)
#pragma unroll
                        for (int nt = 0; nt < NT; nt++)
                            mma16816(acc[mt][nt], af[mt], bf[nt]);
                }
            }
        }
    }

    // ---- epilogue: bias (+relu), direct to gmem
    const int gq = l >> 2;   // row within 16-tile: gq and gq+8
    const int tq = l & 3;    // col pair: tq*2, tq*2+1
#pragma unroll
    for (int mt = 0; mt < 2; mt++) {
        int r0g = row0 + wm * 32 + mt * 16 + gq;
#pragma unroll
        for (int nt = 0; nt < NT; nt++) {
            int col = wn * (NOUT / 2) + nt * 8 + tq * 2;
            float b0 = __ldg(&bias[col]);
            float b1 = __ldg(&bias[col + 1]);
            float d0 = acc[mt][nt][0] + b0;
            float d1 = acc[mt][nt][1] + b1;
            float d2 = acc[mt][nt][2] + b0;
            float d3 = acc[mt][nt][3] + b1;
            if (do_relu) {
                d0 = fmaxf(d0, 0.f);
                d1 = fmaxf(d1, 0.f);
                d2 = fmaxf(d2, 0.f);
                d3 = fmaxf(d3, 0.f);
            }
            if (r0g < M)
                *reinterpret_cast<float2*>(out + (size_t)r0g * NOUT + col) =
                    make_float2(d0, d1);
            if (r0g + 8 < M)
                *reinterpret_cast<float2*>(out + (size_t)(r0g + 8) * NOUT + col) =
                    make_float2(d2, d3);
        }
    }
}

// ---------------- host launch -----------------------------------------------
extern "C" void kernel_launch(void* const* d_in, const int* in_sizes, int n_in,
                              void* d_out, int out_size) {
    const float* x_user = (const float*)d_in[0];
    const float* x_song = (const float*)d_in[1];
    const int* us_src = (const int*)d_in[2];
    const int* us_dst = (const int*)d_in[3];
    const int* su_src = (const int*)d_in[4];
    const int* su_dst = (const int*)d_in[5];
    const float* W1_us_n = (const float*)d_in[6];
    const float* W1_us_s = (const float*)d_in[7];
    const float* b1_us = (const float*)d_in[8];
    const float* W1_su_n = (const float*)d_in[9];
    const float* W1_su_s = (const float*)d_in[10];
    const float* b1_su = (const float*)d_in[11];
    const float* W2_us_n = (const float*)d_in[12];
    const float* W2_us_s = (const float*)d_in[13];
    const float* b2_us = (const float*)d_in[14];
    const float* W2_su_n = (const float*)d_in[15];
    const float* W2_su_s = (const float*)d_in[16];
    const float* b2_su = (const float*)d_in[17];
    float* out = (float*)d_out;

    float *mean_user, *mean_song, *h_user, *h_song;
    int *cnt_user, *cnt_song, *off_user, *off_song, *fin_user, *fin_song;
    int *cur_user, *cur_song, *srt_us, *srt_su, *part;
    char* wimg;
    cudaGetSymbolAddress((void**)&mean_user, g_mean_user);
    cudaGetSymbolAddress((void**)&mean_song, g_mean_song);
    cudaGetSymbolAddress((void**)&h_user, g_h_user);
    cudaGetSymbolAddress((void**)&h_song, g_h_song);
    cudaGetSymbolAddress((void**)&cnt_user, g_cnt_user);
    cudaGetSymbolAddress((void**)&cnt_song, g_cnt_song);
    cudaGetSymbolAddress((void**)&off_user, g_off_user);
    cudaGetSymbolAddress((void**)&off_song, g_off_song);
    cudaGetSymbolAddress((void**)&fin_user, g_fin_user);
    cudaGetSymbolAddress((void**)&fin_song, g_fin_song);
    cudaGetSymbolAddress((void**)&cur_user, g_cur_user);
    cudaGetSymbolAddress((void**)&cur_song, g_cur_song);
    cudaGetSymbolAddress((void**)&srt_us, g_srt_us);
    cudaGetSymbolAddress((void**)&srt_su, g_srt_su);
    cudaGetSymbolAddress((void**)&part, g_part);
    cudaGetSymbolAddress((void**)&wimg, g_wimg);

    const int NB_S = (NS + 1023) / 1024;  // 49
    const int NB_U = (NU + 1023) / 1024;  // 98

    const int SMEM1 = 2 * 128 * 128 + 2 * H1 * 128;  // 65536 B
    const int SMEM2 = 2 * 128 * 128 + 2 * H2 * 128;  // 49152 B
    cudaFuncSetAttribute(sage_gemm_mma<H1>,
                         cudaFuncAttributeMaxDynamicSharedMemorySize, SMEM1);
    cudaFuncSetAttribute(sage_gemm_mma<H2>,
                         cudaFuncAttributeMaxDynamicSharedMemorySize, SMEM2);

    // ---- W image precompute (1 launch; mats: L1 s/n x us/su, then L2)
    {
        WPtrs wp;
        wp.w[0] = W1_us_s; wp.w[1] = W1_us_n; wp.w[2] = W1_su_s; wp.w[3] = W1_su_n;
        wp.w[4] = W2_us_s; wp.w[5] = W2_us_n; wp.w[6] = W2_su_s; wp.w[7] = W2_su_n;
        dim3 g((128 * H1 + 255) / 256, 8);
        wimg_kernel<<<g, 256>>>(wp, wimg);
    }
    const char* i1_us_s = wimg;
    const char* i1_us_n = wimg + 65536;
    const char* i1_su_s = wimg + 2 * 65536;
    const char* i1_su_n = wimg + 3 * 65536;
    const char* i2_us_s = wimg + 4 * 65536;
    const char* i2_us_n = wimg + 4 * 65536 + 32768;
    const char* i2_su_s = wimg + 4 * 65536 + 2 * 32768;
    const char* i2_su_n = wimg + 4 * 65536 + 3 * 32768;

    // ---- CSR build
    zero_int2<<<(NU + 255) / 256, 256>>>(cnt_user, NU, cnt_song, NS);
    count_kernel<<<(NE + 255) / 256, 256>>>(us_dst, su_dst, cnt_song, cnt_user, NE);
    scan_block_dual<<<NB_S + NB_U, 1024>>>(cnt_song, off_song, NS, cnt_user,
                                           off_user, NU, part, NB_S);
    scan_partials_dual<<<1, 128>>>(part, NB_S, NB_U);
    scan_finish_dual<<<(NS + NU + 255) / 256, 256>>>(
        off_song, fin_song, cur_song, NS, off_user, fin_user, cur_user, NU,
        part, NB_S);
    bin_dual<<<(NE + 255) / 256, 256>>>(us_src, us_dst, su_src, su_dst, cur_song,
                                        cur_user, srt_us, srt_su, NE);

    const int naS = (NS + 127) / 128;  // 391
    const int naU = (NU + 127) / 128;  // 782

    // ---- layer 1
    gather_dual<<<(NS + NU + 7) / 8, 256>>>(x_user, srt_us, fin_song, mean_song,
                                            NS, x_song, srt_su, fin_user,
                                            mean_user, NU);
    sage_gemm_mma<H1><<<naS + naU, 256, SMEM1>>>(
        x_song, mean_song, i1_us_s, i1_us_n, b1_us, h_song, NS, naS, x_user,
        mean_user, i1_su_s, i1_su_n, b1_su, h_user, NU, 1);

    // ---- layer 2
    gather_dual<<<(NS + NU + 7) / 8, 256>>>(h_user, srt_us, fin_song, mean_song,
                                            NS, h_song, srt_su, fin_user,
                                            mean_user, NU);
    sage_gemm_mma<H2><<<naS + naU, 256, SMEM2>>>(
        h_song, mean_song, i2_us_s, i2_us_n, b2_us, out + (size_t)NU * H2, NS,
        naS, h_user, mean_user, i2_su_s, i2_su_n, b2_su, out, NU, 0);
}

// round 13
// speedup vs baseline: 1.2144x; 1.0612x over previous
#include <cuda_runtime.h>
#include <cuda_bf16.h>
#include <cstdint>

#define NU 100000
#define NS 50000
#define NE 600000
#define DIN 128
#define H1 128
#define H2 64

#define NBS 391   // ceil(NS/128)
#define NBU 782   // ceil(NU/128)
#define ABLK 65536  // per-128-row-block A image bytes: 2 parts x 2 chunks x 16KB

// ---------------- scratch (device globals; no allocations allowed) ----------
__device__ float g_h_user[NU * H1];
__device__ float g_h_song[NS * H1];
__device__ int g_cnt_user[NU];
__device__ int g_cnt_song[NS];
__device__ int g_off_user[NU];
__device__ int g_off_song[NS];
__device__ int g_fin_user[NU];
__device__ int g_fin_song[NS];
__device__ int g_cur_user[NU];
__device__ int g_cur_song[NS];
__device__ int g_srt_us[NE];
__device__ int g_srt_su[NE];
__device__ int g_part[256];
// W bf16 hi/lo swizzled tile images: 4 H1 mats (64KB each) + 4 H2 mats (32KB)
__device__ __align__(16) char g_wimg[4 * 65536 + 4 * 32768];
// A-operand bf16 hi/lo swizzled block images (zero-init covers pad rows)
__device__ __align__(16) char g_ximg_song[NBS * ABLK];
__device__ __align__(16) char g_ximg_user[NBU * ABLK];
__device__ __align__(16) char g_mimg_song[NBS * ABLK];
__device__ __align__(16) char g_mimg_user[NBU * ABLK];
__device__ __align__(16) char g_himg_song[NBS * ABLK];
__device__ __align__(16) char g_himg_user[NBU * ABLK];

// ---------------- helpers ----------------------------------------------------
__device__ __forceinline__ uint32_t smem_u32(const void* p) {
    uint32_t a;
    asm("{ .reg .u64 t; cvta.to.shared.u64 t, %1; cvt.u32.u64 %0, t; }"
        : "=r"(a) : "l"(p));
    return a;
}
__host__ __device__ __forceinline__ uint32_t sw128(uint32_t off) {
    return off ^ ((off >> 3) & 0x70);
}
__device__ __forceinline__ unsigned long long bfpack4(__nv_bfloat16 a,
                                                      __nv_bfloat16 b,
                                                      __nv_bfloat16 c,
                                                      __nv_bfloat16 d) {
    unsigned int lo = (unsigned int)__bfloat16_as_ushort(a) |
                      ((unsigned int)__bfloat16_as_ushort(b) << 16);
    unsigned int hi = (unsigned int)__bfloat16_as_ushort(c) |
                      ((unsigned int)__bfloat16_as_ushort(d) << 16);
    unsigned long long r;
    asm("mov.b64 %0, {%1, %2};" : "=l"(r) : "r"(lo), "r"(hi));
    return r;
}
__device__ __forceinline__ uint32_t bfpack2(__nv_bfloat16 a, __nv_bfloat16 b) {
    return (uint32_t)__bfloat16_as_ushort(a) |
           ((uint32_t)__bfloat16_as_ushort(b) << 16);
}
__device__ __forceinline__ void cp_async16(uint32_t s, const void* g) {
    asm volatile("cp.async.ca.shared.global [%0], [%1], 16;" :: "r"(s), "l"(g));
}
__device__ __forceinline__ void cp_async_commit() {
    asm volatile("cp.async.commit_group;");
}
__device__ __forceinline__ void cp_async_wait_all() {
    asm volatile("cp.async.wait_group 0;" ::: "memory");
}

__device__ __forceinline__ void ldsm_x4(uint32_t* r, uint32_t addr) {
    asm volatile(
        "ldmatrix.sync.aligned.m8n8.x4.shared.b16 {%0,%1,%2,%3}, [%4];"
        : "=r"(r[0]), "=r"(r[1]), "=r"(r[2]), "=r"(r[3]) : "r"(addr));
}
__device__ __forceinline__ void ldsm_x2(uint32_t* r, uint32_t addr) {
    asm volatile(
        "ldmatrix.sync.aligned.m8n8.x2.shared.b16 {%0,%1}, [%2];"
        : "=r"(r[0]), "=r"(r[1]) : "r"(addr));
}
__device__ __forceinline__ void mma16816(float* d, const uint32_t* a,
                                         const uint32_t* b) {
    asm volatile(
        "mma.sync.aligned.m16n8k16.row.col.f32.bf16.bf16.f32 "
        "{%0,%1,%2,%3}, {%4,%5,%6,%7}, {%8,%9}, {%0,%1,%2,%3};"
        : "+f"(d[0]), "+f"(d[1]), "+f"(d[2]), "+f"(d[3])
        : "r"(a[0]), "r"(a[1]), "r"(a[2]), "r"(a[3]), "r"(b[0]), "r"(b[1]));
}

// Write one A-image row slice: lane covers k = lane*4..lane*4+3 of row r.
// Layout per 128-row block: [hi ch0][hi ch1](32KB) + [lo ch0][lo ch1](32KB);
// within a 16KB chunk tile: sw128(rr*128 + kk*2).
__device__ __forceinline__ void write_row_img(char* img, int r, int lane,
                                              float x0, float x1, float x2,
                                              float x3) {
    uint32_t rb = (uint32_t)r >> 7;
    uint32_t rr = (uint32_t)r & 127;
    char* base = img + (size_t)rb * ABLK + (uint32_t)(lane >> 4) * 16384;
    uint32_t o = sw128(rr * 128 + (uint32_t)(lane & 15) * 8);
    __nv_bfloat16 h0 = __float2bfloat16(x0);
    __nv_bfloat16 h1 = __float2bfloat16(x1);
    __nv_bfloat16 h2 = __float2bfloat16(x2);
    __nv_bfloat16 h3 = __float2bfloat16(x3);
    *reinterpret_cast<unsigned long long*>(base + o) = bfpack4(h0, h1, h2, h3);
    *reinterpret_cast<unsigned long long*>(base + 32768 + o) =
        bfpack4(__float2bfloat16(x0 - __bfloat162float(h0)),
                __float2bfloat16(x1 - __bfloat162float(h1)),
                __float2bfloat16(x2 - __bfloat162float(h2)),
                __float2bfloat16(x3 - __bfloat162float(h3)));
}

// ---------------- W image precompute -----------------------------------------
struct WPtrs {
    const float* w[8];
};
__global__ void wimg_kernel(WPtrs wp, char* img) {
    int mat = blockIdx.y;
    int N = (mat < 4) ? H1 : H2;
    int t = blockIdx.x * 256 + threadIdx.x;
    if (t >= 128 * N) return;
    int k = t / N;
    int n = t % N;
    float w = wp.w[mat][(size_t)k * N + n];
    __nv_bfloat16 hi = __float2bfloat16(w);
    __nv_bfloat16 lo = __float2bfloat16(w - __bfloat162float(hi));
    size_t base = (mat < 4) ? (size_t)mat * 65536
                            : 262144 + (size_t)(mat - 4) * 32768;
    int CHB = N * 128;
    int ch = k >> 6;
    int kk = k & 63;
    uint32_t off = (uint32_t)(ch * CHB) + sw128((uint32_t)(n * 128 + kk * 2));
    *reinterpret_cast<unsigned short*>(img + base + off) =
        __bfloat16_as_ushort(hi);
    *reinterpret_cast<unsigned short*>(img + base + 2 * CHB + off) =
        __bfloat16_as_ushort(lo);
}

// ---------------- X image conversion (both node types, 1 warp/row) -----------
__global__ void ximg_dual(const float* __restrict__ fA, char* iA, int nA,
                          const float* __restrict__ fB, char* iB, int nB) {
    int g = blockIdx.x * 8 + (threadIdx.x >> 5);
    const float* f;
    char* img;
    int r;
    if (g < nA) {
        f = fA; img = iA; r = g;
    } else {
        r = g - nA;
        if (r >= nB) return;
        f = fB; img = iB;
    }
    int lane = threadIdx.x & 31;
    float4 v = *reinterpret_cast<const float4*>(f + (size_t)r * DIN + lane * 4);
    write_row_img(img, r, lane, v.x, v.y, v.z, v.w);
}

// ---------------- CSR build (unchanged, proven) ------------------------------
__global__ void zero_int2(int* a, int na, int* b, int nb) {
    int i = blockIdx.x * blockDim.x + threadIdx.x;
    if (i < na) a[i] = 0;
    if (i < nb) b[i] = 0;
}

__global__ void count_kernel(const int* __restrict__ us_dst,
                             const int* __restrict__ su_dst,
                             int* __restrict__ cnt_song,
                             int* __restrict__ cnt_user, int n) {
    int i = blockIdx.x * blockDim.x + threadIdx.x;
    if (i < n) {
        atomicAdd(&cnt_song[us_dst[i]], 1);
        atomicAdd(&cnt_user[su_dst[i]], 1);
    }
}

__global__ void scan_block_dual(const int* __restrict__ cs, int* __restrict__ os,
                                int ns, const int* __restrict__ cu,
                                int* __restrict__ ou, int nu,
                                int* __restrict__ partials, int nbs) {
    __shared__ int s[1024];
    int b = blockIdx.x;
    const int* in;
    int* out;
    int n, lb;
    if (b < nbs) { in = cs; out = os; n = ns; lb = b; }
    else { in = cu; out = ou; n = nu; lb = b - nbs; }
    int gid = lb * 1024 + threadIdx.x;
    s[threadIdx.x] = (gid < n) ? in[gid] : 0;
    __syncthreads();
#pragma unroll
    for (int d = 1; d < 1024; d <<= 1) {
        int t = (threadIdx.x >= d) ? s[threadIdx.x - d] : 0;
        __syncthreads();
        s[threadIdx.x] += t;
        __syncthreads();
    }
    if (gid < n) out[gid] = s[threadIdx.x];
    if (threadIdx.x == 1023) partials[b] = s[1023];
}

__global__ void scan_partials_dual(int* p, int na, int nb) {
    __shared__ int s[128];
    int t = threadIdx.x;
    s[t] = (t < na) ? p[t] : 0;
    __syncthreads();
#pragma unroll
    for (int d = 1; d < 128; d <<= 1) {
        int v = (t >= d) ? s[t - d] : 0;
        __syncthreads();
        s[t] += v;
        __syncthreads();
    }
    if (t < na) p[t] = s[t];
    __syncthreads();
    s[t] = (t < nb) ? p[na + t] : 0;
    __syncthreads();
#pragma unroll
    for (int d = 1; d < 128; d <<= 1) {
        int v = (t >= d) ? s[t - d] : 0;
        __syncthreads();
        s[t] += v;
        __syncthreads();
    }
    if (t < nb) p[na + t] = s[t];
}

__global__ void scan_finish_dual(const int* __restrict__ rs, int* __restrict__ fs,
                                 int* __restrict__ curs, int ns,
                                 const int* __restrict__ ru, int* __restrict__ fu,
                                 int* __restrict__ curu, int nu,
                                 const int* __restrict__ partials, int nbs) {
    int i = blockIdx.x * blockDim.x + threadIdx.x;
    if (i < ns) {
        int b = i >> 10;
        fs[i] = rs[i] + ((b > 0) ? partials[b - 1] : 0);
        int c = 0;
        if (i > 0) {
            int j = i - 1, bj = j >> 10;
            c = rs[j] + ((bj > 0) ? partials[bj - 1] : 0);
        }
        curs[i] = c;
    }
    int u = i - ns;
    if (u >= 0 && u < nu) {
        int b = u >> 10;
        fu[u] = ru[u] + ((b > 0) ? partials[nbs + b - 1] : 0);
        int c = 0;
        if (u > 0) {
            int j = u - 1, bj = j >> 10;
            c = ru[j] + ((bj > 0) ? partials[nbs + bj - 1] : 0);
        }
        curu[u] = c;
    }
}

__global__ void bin_dual(const int* __restrict__ us_src,
                         const int* __restrict__ us_dst,
                         const int* __restrict__ su_src,
                         const int* __restrict__ su_dst,
                         int* __restrict__ cur_song, int* __restrict__ cur_user,
                         int* __restrict__ srt_us, int* __restrict__ srt_su,
                         int n) {
    int i = blockIdx.x * blockDim.x + threadIdx.x;
    if (i < n) {
        int p0 = atomicAdd(&cur_song[us_dst[i]], 1);
        srt_us[p0] = us_src[i];
        int p1 = atomicAdd(&cur_user[su_dst[i]], 1);
        srt_su[p1] = su_src[i];
    }
}

// ---------------- gather-mean -> bf16 hi/lo image ----------------------------
__global__ void gather_dual(const float* __restrict__ featA,
                            const int* __restrict__ srtA,
                            const int* __restrict__ offA, char* imgA, int nA,
                            const float* __restrict__ featB,
                            const int* __restrict__ srtB,
                            const int* __restrict__ offB, char* imgB, int nB) {
    int g = blockIdx.x * 8 + (threadIdx.x >> 5);
    const float* feat;
    const int* srt;
    const int* off;
    char* img;
    int d;
    if (g < nA) {
        feat = featA; srt = srtA; off = offA; img = imgA; d = g;
    } else {
        d = g - nA;
        if (d >= nB) return;
        feat = featB; srt = srtB; off = offB; img = imgB;
    }
    int lane = threadIdx.x & 31;
    int start = (d > 0) ? off[d - 1] : 0;
    int end = off[d];
    float4 acc = make_float4(0.f, 0.f, 0.f, 0.f);
    int i = start;
    for (; i + 4 <= end; i += 4) {
        int s0 = srt[i], s1 = srt[i + 1], s2 = srt[i + 2], s3 = srt[i + 3];
        float4 a = *reinterpret_cast<const float4*>(feat + (size_t)s0 * DIN + lane * 4);
        float4 b = *reinterpret_cast<const float4*>(feat + (size_t)s1 * DIN + lane * 4);
        float4 c = *reinterpret_cast<const float4*>(feat + (size_t)s2 * DIN + lane * 4);
        float4 e = *reinterpret_cast<const float4*>(feat + (size_t)s3 * DIN + lane * 4);
        acc.x += (a.x + b.x) + (c.x + e.x);
        acc.y += (a.y + b.y) + (c.y + e.y);
        acc.z += (a.z + b.z) + (c.z + e.z);
        acc.w += (a.w + b.w) + (c.w + e.w);
    }
    for (; i < end; ++i) {
        int s0 = srt[i];
        float4 a = *reinterpret_cast<const float4*>(feat + (size_t)s0 * DIN + lane * 4);
        acc.x += a.x; acc.y += a.y; acc.z += a.z; acc.w += a.w;
    }
    int deg = end - start;
    float inv = 1.0f / (float)((deg > 0) ? deg : 1);
    write_row_img(img, d, lane, acc.x * inv, acc.y * inv, acc.z * inv,
                  acc.w * inv);
}

// ---------------- bf16-split tensor-core SAGE GEMM (all-image staging) -------
// D[128, NOUT] = Xself@Ws + Xneigh@Wn, fp32 accum, via mma.sync bf16 hi/lo
// (3 passes: hi*hi + hi*lo + lo*hi). All operands staged by cp.async from
// precomputed swizzled hi/lo images. Optionally emits the output's own
// hi/lo image (layer 1 -> h image for layer 2's self operand).
template <int NOUT>
__global__ void __launch_bounds__(256) sage_gemm_mma(
    const char* __restrict__ iSelfA, const char* __restrict__ iNeighA,
    const char* __restrict__ iWsA, const char* __restrict__ iWnA,
    const float* __restrict__ bA, float* __restrict__ outA, char* himgA,
    int MA, int nblkA,
    const char* __restrict__ iSelfB, const char* __restrict__ iNeighB,
    const char* __restrict__ iWsB, const char* __restrict__ iWnB,
    const float* __restrict__ bB, float* __restrict__ outB, char* himgB,
    int MB, int do_relu) {
    constexpr int BM = 128;
    constexpr int NT = NOUT / 16;        // n-tiles per warp: 8 / 4
    constexpr int A_BYTES = BM * 128;    // 16KB per part-chunk tile
    constexpr int B_BYTES = NOUT * 128;  // chunk bytes
    constexpr int SWP = B_BYTES / (256 * 16);  // B cp sweeps: 4 (H1) / 2 (H2)
    extern __shared__ char smem[];
    char* A_HI = smem;
    char* A_LO = smem + A_BYTES;
    char* B_HI = smem + 2 * A_BYTES;
    char* B_LO = smem + 2 * A_BYTES + B_BYTES;

    // side dispatch
    const char* iSelf; const char* iNeigh; const char* iWs; const char* iWn;
    const float* bias; float* out; char* himg; int M, bid;
    if ((int)blockIdx.x < nblkA) {
        iSelf = iSelfA; iNeigh = iNeighA; iWs = iWsA; iWn = iWnA; bias = bA;
        out = outA; himg = himgA; M = MA; bid = blockIdx.x;
    } else {
        iSelf = iSelfB; iNeigh = iNeighB; iWs = iWsB; iWn = iWnB; bias = bB;
        out = outB; himg = himgB; M = MB; bid = blockIdx.x - nblkA;
    }

    const int tid = threadIdx.x;
    const int w = tid >> 5;
    const int l = tid & 31;
    const int wm = w & 3;      // 4 warps along M (32 rows each)
    const int wn = w >> 2;     // 2 warps along N (NOUT/2 cols each)
    const int row0 = bid * BM;

    const uint32_t saAH = smem_u32(A_HI);
    const uint32_t saAL = smem_u32(A_LO);
    const uint32_t saBH = smem_u32(B_HI);
    const uint32_t saBL = smem_u32(B_LO);

    float acc[2][NT][4];
#pragma unroll
    for (int mt = 0; mt < 2; mt++)
#pragma unroll
        for (int nt = 0; nt < NT; nt++)
#pragma unroll
            for (int j = 0; j < 4; j++) acc[mt][nt][j] = 0.f;

    // ldmatrix per-lane addresses (within-chunk, before adding kt offset)
    const uint32_t a_m = (uint32_t)(l & 15);
    const uint32_t a_ch = (uint32_t)(l >> 4) * 8;
    const uint32_t b_nl = (uint32_t)(l & 7);
    const uint32_t b_ch = (uint32_t)((l >> 3) & 1) * 8;

    for (int op = 0; op < 2; ++op) {
        const char* iA = (op ? iNeigh : iSelf) + (size_t)bid * ABLK;
        const char* iW = op ? iWn : iWs;
        for (int ch = 0; ch < 2; ++ch) {
            __syncthreads();
            // ---- A tiles: cp.async of swizzled hi/lo image (16KB each)
            {
                const char* aimg = iA + ch * 16384;
#pragma unroll
                for (int j = 0; j < 4; j++) {
                    uint32_t o = (uint32_t)(tid * 16 + j * 4096);
                    cp_async16(saAH + o, aimg + o);
                    cp_async16(saAL + o, aimg + 32768 + o);
                }
            }
            // ---- B tiles: cp.async of swizzled hi/lo image
            {
                const char* bimg = iW + ch * B_BYTES;
#pragma unroll
                for (int j = 0; j < SWP; j++) {
                    uint32_t o = (uint32_t)(tid * 16 + j * 4096);
                    cp_async16(saBH + o, bimg + o);
                    cp_async16(saBL + o, bimg + 2 * B_BYTES + o);
                }
            }
            cp_async_commit();
            cp_async_wait_all();
            __syncthreads();

            // ---- 3 passes x 4 k16-steps of mma
#pragma unroll
            for (int p = 0; p < 3; p++) {
                const uint32_t sa = (p == 2) ? saAL : saAH;
                const uint32_t sb = (p == 1) ? saBL : saBH;
#pragma unroll
                for (int kt = 0; kt < 4; kt++) {
                    uint32_t af[2][4];
#pragma unroll
                    for (int mt = 0; mt < 2; mt++) {
                        uint32_t r = (uint32_t)(wm * 32 + mt * 16) + a_m;
                        uint32_t c = (uint32_t)(kt * 16) + a_ch;
                        ldsm_x4(af[mt], sa + sw128(r * 128 + c * 2));
                    }
                    uint32_t bf[NT][2];
#pragma unroll
                    for (int nt = 0; nt < NT; nt++) {
                        uint32_t n = (uint32_t)(wn * (NOUT / 2) + nt * 8) + b_nl;
                        uint32_t c = (uint32_t)(kt * 16) + b_ch;
                        ldsm_x2(bf[nt], sb + sw128(n * 128 + c * 2));
                    }
#pragma unroll
                    for (int mt = 0; mt < 2; mt++)
#pragma unroll
                        for (int nt = 0; nt < NT; nt++)
                            mma16816(acc[mt][nt], af[mt], bf[nt]);
                }
            }
        }
    }

    // ---- epilogue: bias (+relu), fp32 out, optional hi/lo image of output
    const int gq = l >> 2;   // row within 16-tile: gq and gq+8
    const int tq = l & 3;    // col pair: tq*2, tq*2+1
    char* hb = himg ? himg + (size_t)bid * ABLK : nullptr;
#pragma unroll
    for (int mt = 0; mt < 2; mt++) {
        int rrl = wm * 32 + mt * 16 + gq;
        int r0g = row0 + rrl;
        bool ok0 = r0g < M;
        bool ok8 = (r0g + 8) < M;
#pragma unroll
        for (int nt = 0; nt < NT; nt++) {
            int col = wn * (NOUT / 2) + nt * 8 + tq * 2;
            float b0 = __ldg(&bias[col]);
            float b1 = __ldg(&bias[col + 1]);
            float d0 = acc[mt][nt][0] + b0;
            float d1 = acc[mt][nt][1] + b1;
            float d2 = acc[mt][nt][2] + b0;
            float d3 = acc[mt][nt][3] + b1;
            if (do_relu) {
                d0 = fmaxf(d0, 0.f);
                d1 = fmaxf(d1, 0.f);
                d2 = fmaxf(d2, 0.f);
                d3 = fmaxf(d3, 0.f);
            }
            if (ok0)
                *reinterpret_cast<float2*>(out + (size_t)r0g * NOUT + col) =
                    make_float2(d0, d1);
            if (ok8)
                *reinterpret_cast<float2*>(out + (size_t)(r0g + 8) * NOUT + col) =
                    make_float2(d2, d3);
            if (hb) {
                int chc = col >> 6;
                int kk = col & 63;
                char* hc = hb + chc * 16384;
                if (ok0) {
                    uint32_t o = sw128((uint32_t)(rrl * 128 + kk * 2));
                    __nv_bfloat16 a0 = __float2bfloat16(d0);
                    __nv_bfloat16 a1 = __float2bfloat16(d1);
                    *reinterpret_cast<uint32_t*>(hc + o) = bfpack2(a0, a1);
                    *reinterpret_cast<uint32_t*>(hc + 32768 + o) = bfpack2(
                        __float2bfloat16(d0 - __bfloat162float(a0)),
                        __float2bfloat16(d1 - __bfloat162float(a1)));
                }
                if (ok8) {
                    uint32_t o = sw128((uint32_t)((rrl + 8) * 128 + kk * 2));
                    __nv_bfloat16 a2 = __float2bfloat16(d2);
                    __nv_bfloat16 a3 = __float2bfloat16(d3);
                    *reinterpret_cast<uint32_t*>(hc + o) = bfpack2(a2, a3);
                    *reinterpret_cast<uint32_t*>(hc + 32768 + o) = bfpack2(
                        __float2bfloat16(d2 - __bfloat162float(a2)),
                        __float2bfloat16(d3 - __bfloat162float(a3)));
                }
            }
        }
    }
}

// ---------------- host launch -----------------------------------------------
extern "C" void kernel_launch(void* const* d_in, const int* in_sizes, int n_in,
                              void* d_out, int out_size) {
    const float* x_user = (const float*)d_in[0];
    const float* x_song = (const float*)d_in[1];
    const int* us_src = (const int*)d_in[2];
    const int* us_dst = (const int*)d_in[3];
    const int* su_src = (const int*)d_in[4];
    const int* su_dst = (const int*)d_in[5];
    const float* W1_us_n = (const float*)d_in[6];
    const float* W1_us_s = (const float*)d_in[7];
    const float* b1_us = (const float*)d_in[8];
    const float* W1_su_n = (const float*)d_in[9];
    const float* W1_su_s = (const float*)d_in[10];
    const float* b1_su = (const float*)d_in[11];
    const float* W2_us_n = (const float*)d_in[12];
    const float* W2_us_s = (const float*)d_in[13];
    const float* b2_us = (const float*)d_in[14];
    const float* W2_su_n = (const float*)d_in[15];
    const float* W2_su_s = (const float*)d_in[16];
    const float* b2_su = (const float*)d_in[17];
    float* out = (float*)d_out;

    float *h_user, *h_song;
    int *cnt_user, *cnt_song, *off_user, *off_song, *fin_user, *fin_song;
    int *cur_user, *cur_song, *srt_us, *srt_su, *part;
    char *wimg, *ximg_s, *ximg_u, *mimg_s, *mimg_u, *himg_s, *himg_u;
    cudaGetSymbolAddress((void**)&h_user, g_h_user);
    cudaGetSymbolAddress((void**)&h_song, g_h_song);
    cudaGetSymbolAddress((void**)&cnt_user, g_cnt_user);
    cudaGetSymbolAddress((void**)&cnt_song, g_cnt_song);
    cudaGetSymbolAddress((void**)&off_user, g_off_user);
    cudaGetSymbolAddress((void**)&off_song, g_off_song);
    cudaGetSymbolAddress((void**)&fin_user, g_fin_user);
    cudaGetSymbolAddress((void**)&fin_song, g_fin_song);
    cudaGetSymbolAddress((void**)&cur_user, g_cur_user);
    cudaGetSymbolAddress((void**)&cur_song, g_cur_song);
    cudaGetSymbolAddress((void**)&srt_us, g_srt_us);
    cudaGetSymbolAddress((void**)&srt_su, g_srt_su);
    cudaGetSymbolAddress((void**)&part, g_part);
    cudaGetSymbolAddress((void**)&wimg, g_wimg);
    cudaGetSymbolAddress((void**)&ximg_s, g_ximg_song);
    cudaGetSymbolAddress((void**)&ximg_u, g_ximg_user);
    cudaGetSymbolAddress((void**)&mimg_s, g_mimg_song);
    cudaGetSymbolAddress((void**)&mimg_u, g_mimg_user);
    cudaGetSymbolAddress((void**)&himg_s, g_himg_song);
    cudaGetSymbolAddress((void**)&himg_u, g_himg_user);

    const int NB_S = (NS + 1023) / 1024;  // 49
    const int NB_U = (NU + 1023) / 1024;  // 98

    const int SMEM1 = 2 * 128 * 128 + 2 * H1 * 128;  // 65536 B
    const int SMEM2 = 2 * 128 * 128 + 2 * H2 * 128;  // 49152 B
    cudaFuncSetAttribute(sage_gemm_mma<H1>,
                         cudaFuncAttributeMaxDynamicSharedMemorySize, SMEM1);
    cudaFuncSetAttribute(sage_gemm_mma<H2>,
                         cudaFuncAttributeMaxDynamicSharedMemorySize, SMEM2);

    // ---- W image precompute
    {
        WPtrs wp;
        wp.w[0] = W1_us_s; wp.w[1] = W1_us_n; wp.w[2] = W1_su_s; wp.w[3] = W1_su_n;
        wp.w[4] = W2_us_s; wp.w[5] = W2_us_n; wp.w[6] = W2_su_s; wp.w[7] = W2_su_n;
        dim3 g((128 * H1 + 255) / 256, 8);
        wimg_kernel<<<g, 256>>>(wp, wimg);
    }
    const char* i1_us_s = wimg;
    const char* i1_us_n = wimg + 65536;
    const char* i1_su_s = wimg + 2 * 65536;
    const char* i1_su_n = wimg + 3 * 65536;
    const char* i2_us_s = wimg + 4 * 65536;
    const char* i2_us_n = wimg + 4 * 65536 + 32768;
    const char* i2_su_s = wimg + 4 * 65536 + 2 * 32768;
    const char* i2_su_n = wimg + 4 * 65536 + 3 * 32768;

    // ---- X images (self operand for layer 1)
    ximg_dual<<<(NS + NU + 7) / 8, 256>>>(x_song, ximg_s, NS, x_user, ximg_u, NU);

    // ---- CSR build
    zero_int2<<<(NU + 255) / 256, 256>>>(cnt_user, NU, cnt_song, NS);
    count_kernel<<<(NE + 255) / 256, 256>>>(us_dst, su_dst, cnt_song, cnt_user, NE);
    scan_block_dual<<<NB_S + NB_U, 1024>>>(cnt_song, off_song, NS, cnt_user,
                                           off_user, NU, part, NB_S);
    scan_partials_dual<<<1, 128>>>(part, NB_S, NB_U);
    scan_finish_dual<<<(NS + NU + 255) / 256, 256>>>(
        off_song, fin_song, cur_song, NS, off_user, fin_user, cur_user, NU,
        part, NB_S);
    bin_dual<<<(NE + 255) / 256, 256>>>(us_src, us_dst, su_src, su_dst, cur_song,
                                        cur_user, srt_us, srt_su, NE);

    // ---- layer 1: gather means (of x) into mean images, then GEMM
    gather_dual<<<(NS + NU + 7) / 8, 256>>>(x_user, srt_us, fin_song, mimg_s, NS,
                                            x_song, srt_su, fin_user, mimg_u, NU);
    sage_gemm_mma<H1><<<NBS + NBU, 256, SMEM1>>>(
        ximg_s, mimg_s, i1_us_s, i1_us_n, b1_us, h_song, himg_s, NS, NBS,
        ximg_u, mimg_u, i1_su_s, i1_su_n, b1_su, h_user, himg_u, NU, 1);

    // ---- layer 2: gather means (of h) into mean images, then GEMM to output
    gather_dual<<<(NS + NU + 7) / 8, 256>>>(h_user, srt_us, fin_song, mimg_s, NS,
                                            h_song, srt_su, fin_user, mimg_u, NU);
    sage_gemm_mma<H2><<<NBS + NBU, 256, SMEM2>>>(
        himg_s, mimg_s, i2_us_s, i2_us_n, b2_us, out + (size_t)NU * H2, nullptr,
        NS, NBS, himg_u, mimg_u, i2_su_s, i2_su_n, b2_su, out, nullptr, NU, 0);
}

// round 14
// speedup vs baseline: 1.2461x; 1.0261x over previous
#include <cuda_runtime.h>
#include <cuda_bf16.h>
#include <cstdint>

#define NU 100000
#define NS 50000
#define NE 600000
#define DIN 128
#define H1 128
#define H2 64

#define NBS 391   // ceil(NS/128)
#define NBU 782   // ceil(NU/128)
#define ABLK 65536  // per-128-row-block A image bytes: 2 parts x 2 chunks x 16KB

// ---------------- scratch (device globals; no allocations allowed) ----------
__device__ float g_p_user[NU * H2];   // h_user @ W2_us_n (projected, for song agg)
__device__ float g_p_song[NS * H2];   // h_song @ W2_su_n (projected, for user agg)
__device__ float g_zero64[64];        // zero bias for projection segments
__device__ int g_cnt_user[NU];
__device__ int g_cnt_song[NS];
__device__ int g_off_user[NU];
__device__ int g_off_song[NS];
__device__ int g_fin_user[NU];
__device__ int g_fin_song[NS];
__device__ int g_cur_user[NU];
__device__ int g_cur_song[NS];
__device__ int g_srt_us[NE];
__device__ int g_srt_su[NE];
__device__ int g_part[256];
// W bf16 hi/lo swizzled tile images: 4 H1 mats (64KB each) + 4 H2 mats (32KB)
__device__ __align__(16) char g_wimg[4 * 65536 + 4 * 32768];
// A-operand bf16 hi/lo swizzled block images (zero-init covers pad rows)
__device__ __align__(16) char g_ximg_song[NBS * ABLK];
__device__ __align__(16) char g_ximg_user[NBU * ABLK];
__device__ __align__(16) char g_mimg_song[NBS * ABLK];
__device__ __align__(16) char g_mimg_user[NBU * ABLK];
__device__ __align__(16) char g_himg_song[NBS * ABLK];
__device__ __align__(16) char g_himg_user[NBU * ABLK];

// ---------------- helpers ----------------------------------------------------
__device__ __forceinline__ uint32_t smem_u32(const void* p) {
    uint32_t a;
    asm("{ .reg .u64 t; cvta.to.shared.u64 t, %1; cvt.u32.u64 %0, t; }"
        : "=r"(a) : "l"(p));
    return a;
}
__host__ __device__ __forceinline__ uint32_t sw128(uint32_t off) {
    return off ^ ((off >> 3) & 0x70);
}
__device__ __forceinline__ unsigned long long bfpack4(__nv_bfloat16 a,
                                                      __nv_bfloat16 b,
                                                      __nv_bfloat16 c,
                                                      __nv_bfloat16 d) {
    unsigned int lo = (unsigned int)__bfloat16_as_ushort(a) |
                      ((unsigned int)__bfloat16_as_ushort(b) << 16);
    unsigned int hi = (unsigned int)__bfloat16_as_ushort(c) |
                      ((unsigned int)__bfloat16_as_ushort(d) << 16);
    unsigned long long r;
    asm("mov.b64 %0, {%1, %2};" : "=l"(r) : "r"(lo), "r"(hi));
    return r;
}
__device__ __forceinline__ uint32_t bfpack2(__nv_bfloat16 a, __nv_bfloat16 b) {
    return (uint32_t)__bfloat16_as_ushort(a) |
           ((uint32_t)__bfloat16_as_ushort(b) << 16);
}
__device__ __forceinline__ void cp_async16(uint32_t s, const void* g) {
    asm volatile("cp.async.ca.shared.global [%0], [%1], 16;" :: "r"(s), "l"(g));
}
__device__ __forceinline__ void cp_async_commit() {
    asm volatile("cp.async.commit_group;");
}
__device__ __forceinline__ void cp_async_wait_all() {
    asm volatile("cp.async.wait_group 0;" ::: "memory");
}

__device__ __forceinline__ void ldsm_x4(uint32_t* r, uint32_t addr) {
    asm volatile(
        "ldmatrix.sync.aligned.m8n8.x4.shared.b16 {%0,%1,%2,%3}, [%4];"
        : "=r"(r[0]), "=r"(r[1]), "=r"(r[2]), "=r"(r[3]) : "r"(addr));
}
__device__ __forceinline__ void ldsm_x2(uint32_t* r, uint32_t addr) {
    asm volatile(
        "ldmatrix.sync.aligned.m8n8.x2.shared.b16 {%0,%1}, [%2];"
        : "=r"(r[0]), "=r"(r[1]) : "r"(addr));
}
__device__ __forceinline__ void mma16816(float* d, const uint32_t* a,
                                         const uint32_t* b) {
    asm volatile(
        "mma.sync.aligned.m16n8k16.row.col.f32.bf16.bf16.f32 "
        "{%0,%1,%2,%3}, {%4,%5,%6,%7}, {%8,%9}, {%0,%1,%2,%3};"
        : "+f"(d[0]), "+f"(d[1]), "+f"(d[2]), "+f"(d[3])
        : "r"(a[0]), "r"(a[1]), "r"(a[2]), "r"(a[3]), "r"(b[0]), "r"(b[1]));
}

// Write one A-image row slice: lane covers k = lane*4..lane*4+3 of row r.
__device__ __forceinline__ void write_row_img(char* img, int r, int lane,
                                              float x0, float x1, float x2,
                                              float x3) {
    uint32_t rb = (uint32_t)r >> 7;
    uint32_t rr = (uint32_t)r & 127;
    char* base = img + (size_t)rb * ABLK + (uint32_t)(lane >> 4) * 16384;
    uint32_t o = sw128(rr * 128 + (uint32_t)(lane & 15) * 8);
    __nv_bfloat16 h0 = __float2bfloat16(x0);
    __nv_bfloat16 h1 = __float2bfloat16(x1);
    __nv_bfloat16 h2 = __float2bfloat16(x2);
    __nv_bfloat16 h3 = __float2bfloat16(x3);
    *reinterpret_cast<unsigned long long*>(base + o) = bfpack4(h0, h1, h2, h3);
    *reinterpret_cast<unsigned long long*>(base + 32768 + o) =
        bfpack4(__float2bfloat16(x0 - __bfloat162float(h0)),
                __float2bfloat16(x1 - __bfloat162float(h1)),
                __float2bfloat16(x2 - __bfloat162float(h2)),
                __float2bfloat16(x3 - __bfloat162float(h3)));
}

// ---------------- W image precompute -----------------------------------------
struct WPtrs {
    const float* w[8];
};
__global__ void wimg_kernel(WPtrs wp, char* img) {
    int mat = blockIdx.y;
    int N = (mat < 4) ? H1 : H2;
    int t = blockIdx.x * 256 + threadIdx.x;
    if (t >= 128 * N) return;
    int k = t / N;
    int n = t % N;
    float w = wp.w[mat][(size_t)k * N + n];
    __nv_bfloat16 hi = __float2bfloat16(w);
    __nv_bfloat16 lo = __float2bfloat16(w - __bfloat162float(hi));
    size_t base = (mat < 4) ? (size_t)mat * 65536
                            : 262144 + (size_t)(mat - 4) * 32768;
    int CHB = N * 128;
    int ch = k >> 6;
    int kk = k & 63;
    uint32_t off = (uint32_t)(ch * CHB) + sw128((uint32_t)(n * 128 + kk * 2));
    *reinterpret_cast<unsigned short*>(img + base + off) =
        __bfloat16_as_ushort(hi);
    *reinterpret_cast<unsigned short*>(img + base + 2 * CHB + off) =
        __bfloat16_as_ushort(lo);
}

// ---------------- X image conversion (both node types, 1 warp/row) -----------
__global__ void ximg_dual(const float* __restrict__ fA, char* iA, int nA,
                          const float* __restrict__ fB, char* iB, int nB) {
    int g = blockIdx.x * 8 + (threadIdx.x >> 5);
    const float* f;
    char* img;
    int r;
    if (g < nA) {
        f = fA; img = iA; r = g;
    } else {
        r = g - nA;
        if (r >= nB) return;
        f = fB; img = iB;
    }
    int lane = threadIdx.x & 31;
    float4 v = *reinterpret_cast<const float4*>(f + (size_t)r * DIN + lane * 4);
    write_row_img(img, r, lane, v.x, v.y, v.z, v.w);
}

// ---------------- CSR build (unchanged, proven) ------------------------------
__global__ void zero_int2(int* a, int na, int* b, int nb) {
    int i = blockIdx.x * blockDim.x + threadIdx.x;
    if (i < na) a[i] = 0;
    if (i < nb) b[i] = 0;
}

__global__ void count_kernel(const int* __restrict__ us_dst,
                             const int* __restrict__ su_dst,
                             int* __restrict__ cnt_song,
                             int* __restrict__ cnt_user, int n) {
    int i = blockIdx.x * blockDim.x + threadIdx.x;
    if (i < n) {
        atomicAdd(&cnt_song[us_dst[i]], 1);
        atomicAdd(&cnt_user[su_dst[i]], 1);
    }
}

__global__ void scan_block_dual(const int* __restrict__ cs, int* __restrict__ os,
                                int ns, const int* __restrict__ cu,
                                int* __restrict__ ou, int nu,
                                int* __restrict__ partials, int nbs) {
    __shared__ int s[1024];
    int b = blockIdx.x;
    const int* in;
    int* out;
    int n, lb;
    if (b < nbs) { in = cs; out = os; n = ns; lb = b; }
    else { in = cu; out = ou; n = nu; lb = b - nbs; }
    int gid = lb * 1024 + threadIdx.x;
    s[threadIdx.x] = (gid < n) ? in[gid] : 0;
    __syncthreads();
#pragma unroll
    for (int d = 1; d < 1024; d <<= 1) {
        int t = (threadIdx.x >= d) ? s[threadIdx.x - d] : 0;
        __syncthreads();
        s[threadIdx.x] += t;
        __syncthreads();
    }
    if (gid < n) out[gid] = s[threadIdx.x];
    if (threadIdx.x == 1023) partials[b] = s[1023];
}

__global__ void scan_partials_dual(int* p, int na, int nb) {
    __shared__ int s[128];
    int t = threadIdx.x;
    s[t] = (t < na) ? p[t] : 0;
    __syncthreads();
#pragma unroll
    for (int d = 1; d < 128; d <<= 1) {
        int v = (t >= d) ? s[t - d] : 0;
        __syncthreads();
        s[t] += v;
        __syncthreads();
    }
    if (t < na) p[t] = s[t];
    __syncthreads();
    s[t] = (t < nb) ? p[na + t] : 0;
    __syncthreads();
#pragma unroll
    for (int d = 1; d < 128; d <<= 1) {
        int v = (t >= d) ? s[t - d] : 0;
        __syncthreads();
        s[t] += v;
        __syncthreads();
    }
    if (t < nb) p[na + t] = s[t];
}

__global__ void scan_finish_dual(const int* __restrict__ rs, int* __restrict__ fs,
                                 int* __restrict__ curs, int ns,
                                 const int* __restrict__ ru, int* __restrict__ fu,
                                 int* __restrict__ curu, int nu,
                                 const int* __restrict__ partials, int nbs) {
    int i = blockIdx.x * blockDim.x + threadIdx.x;
    if (i < ns) {
        int b = i >> 10;
        fs[i] = rs[i] + ((b > 0) ? partials[b - 1] : 0);
        int c = 0;
        if (i > 0) {
            int j = i - 1, bj = j >> 10;
            c = rs[j] + ((bj > 0) ? partials[bj - 1] : 0);
        }
        curs[i] = c;
    }
    int u = i - ns;
    if (u >= 0 && u < nu) {
        int b = u >> 10;
        fu[u] = ru[u] + ((b > 0) ? partials[nbs + b - 1] : 0);
        int c = 0;
        if (u > 0) {
            int j = u - 1, bj = j >> 10;
            c = ru[j] + ((bj > 0) ? partials[nbs + bj - 1] : 0);
        }
        curu[u] = c;
    }
}

__global__ void bin_dual(const int* __restrict__ us_src,
                         const int* __restrict__ us_dst,
                         const int* __restrict__ su_src,
                         const int* __restrict__ su_dst,
                         int* __restrict__ cur_song, int* __restrict__ cur_user,
                         int* __restrict__ srt_us, int* __restrict__ srt_su,
                         int n) {
    int i = blockIdx.x * blockDim.x + threadIdx.x;
    if (i < n) {
        int p0 = atomicAdd(&cur_song[us_dst[i]], 1);
        srt_us[p0] = us_src[i];
        int p1 = atomicAdd(&cur_user[su_dst[i]], 1);
        srt_su[p1] = su_src[i];
    }
}

// ---------------- gather-mean (x, 128-dim) -> bf16 hi/lo image ---------------
__global__ void gather_dual(const float* __restrict__ featA,
                            const int* __restrict__ srtA,
                            const int* __restrict__ offA, char* imgA, int nA,
                            const float* __restrict__ featB,
                            const int* __restrict__ srtB,
                            const int* __restrict__ offB, char* imgB, int nB) {
    int g = blockIdx.x * 8 + (threadIdx.x >> 5);
    const float* feat;
    const int* srt;
    const int* off;
    char* img;
    int d;
    if (g < nA) {
        feat = featA; srt = srtA; off = offA; img = imgA; d = g;
    } else {
        d = g - nA;
        if (d >= nB) return;
        feat = featB; srt = srtB; off = offB; img = imgB;
    }
    int lane = threadIdx.x & 31;
    int start = (d > 0) ? off[d - 1] : 0;
    int end = off[d];
    float4 acc = make_float4(0.f, 0.f, 0.f, 0.f);
    int i = start;
    for (; i + 4 <= end; i += 4) {
        int s0 = srt[i], s1 = srt[i + 1], s2 = srt[i + 2], s3 = srt[i + 3];
        float4 a = *reinterpret_cast<const float4*>(feat + (size_t)s0 * DIN + lane * 4);
        float4 b = *reinterpret_cast<const float4*>(feat + (size_t)s1 * DIN + lane * 4);
        float4 c = *reinterpret_cast<const float4*>(feat + (size_t)s2 * DIN + lane * 4);
        float4 e = *reinterpret_cast<const float4*>(feat + (size_t)s3 * DIN + lane * 4);
        acc.x += (a.x + b.x) + (c.x + e.x);
        acc.y += (a.y + b.y) + (c.y + e.y);
        acc.z += (a.z + b.z) + (c.z + e.z);
        acc.w += (a.w + b.w) + (c.w + e.w);
    }
    for (; i < end; ++i) {
        int s0 = srt[i];
        float4 a = *reinterpret_cast<const float4*>(feat + (size_t)s0 * DIN + lane * 4);
        acc.x += a.x; acc.y += a.y; acc.z += a.z; acc.w += a.w;
    }
    int deg = end - start;
    float inv = 1.0f / (float)((deg > 0) ? deg : 1);
    write_row_img(img, d, lane, acc.x * inv, acc.y * inv, acc.z * inv,
                  acc.w * inv);
}

// ---------------- gather-mean of projected (64-dim) + add into out -----------
__global__ void gather_add_dual(const float* __restrict__ pA,
                                const int* __restrict__ srtA,
                                const int* __restrict__ offA, float* outA,
                                int nA, const float* __restrict__ pB,
                                const int* __restrict__ srtB,
                                const int* __restrict__ offB, float* outB,
                                int nB) {
    int g = blockIdx.x * 8 + (threadIdx.x >> 5);
    const float* p;
    const int* srt;
    const int* off;
    float* outp;
    int d;
    if (g < nA) {
        p = pA; srt = srtA; off = offA; outp = outA; d = g;
    } else {
        d = g - nA;
        if (d >= nB) return;
        p = pB; srt = srtB; off = offB; outp = outB;
    }
    int lane = threadIdx.x & 31;
    int start = (d > 0) ? off[d - 1] : 0;
    int end = off[d];
    float2 acc = make_float2(0.f, 0.f);
    int i = start;
    for (; i + 4 <= end; i += 4) {
        int s0 = srt[i], s1 = srt[i + 1], s2 = srt[i + 2], s3 = srt[i + 3];
        float2 a = *reinterpret_cast<const float2*>(p + (size_t)s0 * H2 + lane * 2);
        float2 b = *reinterpret_cast<const float2*>(p + (size_t)s1 * H2 + lane * 2);
        float2 c = *reinterpret_cast<const float2*>(p + (size_t)s2 * H2 + lane * 2);
        float2 e = *reinterpret_cast<const float2*>(p + (size_t)s3 * H2 + lane * 2);
        acc.x += (a.x + b.x) + (c.x + e.x);
        acc.y += (a.y + b.y) + (c.y + e.y);
    }
    for (; i < end; ++i) {
        int s0 = srt[i];
        float2 a = *reinterpret_cast<const float2*>(p + (size_t)s0 * H2 + lane * 2);
        acc.x += a.x;
        acc.y += a.y;
    }
    int deg = end - start;
    float inv = 1.0f / (float)((deg > 0) ? deg : 1);
    float2* o = reinterpret_cast<float2*>(outp + (size_t)d * H2 + lane * 2);
    float2 cur = *o;
    cur.x += acc.x * inv;
    cur.y += acc.y * inv;
    *o = cur;
}

// ---------------- layer-1 dual SAGE GEMM (image staging, himg-only output) ---
template <int NOUT>
__global__ void __launch_bounds__(256) sage_gemm_mma(
    const char* __restrict__ iSelfA, const char* __restrict__ iNeighA,
    const char* __restrict__ iWsA, const char* __restrict__ iWnA,
    const float* __restrict__ bA, float* __restrict__ outA, char* himgA,
    int MA, int nblkA,
    const char* __restrict__ iSelfB, const char* __restrict__ iNeighB,
    const char* __restrict__ iWsB, const char* __restrict__ iWnB,
    const float* __restrict__ bB, float* __restrict__ outB, char* himgB,
    int MB, int do_relu) {
    constexpr int BM = 128;
    constexpr int NT = NOUT / 16;
    constexpr int A_BYTES = BM * 128;
    constexpr int B_BYTES = NOUT * 128;
    constexpr int SWP = B_BYTES / (256 * 16);
    extern __shared__ char smem[];
    char* A_HI = smem;
    char* A_LO = smem + A_BYTES;
    char* B_HI = smem + 2 * A_BYTES;
    char* B_LO = smem + 2 * A_BYTES + B_BYTES;

    const char* iSelf; const char* iNeigh; const char* iWs; const char* iWn;
    const float* bias; float* out; char* himg; int M, bid;
    if ((int)blockIdx.x < nblkA) {
        iSelf = iSelfA; iNeigh = iNeighA; iWs = iWsA; iWn = iWnA; bias = bA;
        out = outA; himg = himgA; M = MA; bid = blockIdx.x;
    } else {
        iSelf = iSelfB; iNeigh = iNeighB; iWs = iWsB; iWn = iWnB; bias = bB;
        out = outB; himg = himgB; M = MB; bid = blockIdx.x - nblkA;
    }

    const int tid = threadIdx.x;
    const int w = tid >> 5;
    const int l = tid & 31;
    const int wm = w & 3;
    const int wn = w >> 2;
    const int row0 = bid * BM;

    const uint32_t saAH = smem_u32(A_HI);
    const uint32_t saAL = smem_u32(A_LO);
    const uint32_t saBH = smem_u32(B_HI);
    const uint32_t saBL = smem_u32(B_LO);

    float acc[2][NT][4];
#pragma unroll
    for (int mt = 0; mt < 2; mt++)
#pragma unroll
        for (int nt = 0; nt < NT; nt++)
#pragma unroll
            for (int j = 0; j < 4; j++) acc[mt][nt][j] = 0.f;

    const uint32_t a_m = (uint32_t)(l & 15);
    const uint32_t a_ch = (uint32_t)(l >> 4) * 8;
    const uint32_t b_nl = (uint32_t)(l & 7);
    const uint32_t b_ch = (uint32_t)((l >> 3) & 1) * 8;

    for (int op = 0; op < 2; ++op) {
        const char* iA = (op ? iNeigh : iSelf) + (size_t)bid * ABLK;
        const char* iW = op ? iWn : iWs;
        for (int ch = 0; ch < 2; ++ch) {
            __syncthreads();
            {
                const char* aimg = iA + ch * 16384;
#pragma unroll
                for (int j = 0; j < 4; j++) {
                    uint32_t o = (uint32_t)(tid * 16 + j * 4096);
                    cp_async16(saAH + o, aimg + o);
                    cp_async16(saAL + o, aimg + 32768 + o);
                }
            }
            {
                const char* bimg = iW + ch * B_BYTES;
#pragma unroll
                for (int j = 0; j < SWP; j++) {
                    uint32_t o = (uint32_t)(tid * 16 + j * 4096);
                    cp_async16(saBH + o, bimg + o);
                    cp_async16(saBL + o, bimg + 2 * B_BYTES + o);
                }
            }
            cp_async_commit();
            cp_async_wait_all();
            __syncthreads();

#pragma unroll
            for (int p = 0; p < 3; p++) {
                const uint32_t sa = (p == 2) ? saAL : saAH;
                const uint32_t sb = (p == 1) ? saBL : saBH;
#pragma unroll
                for (int kt = 0; kt < 4; kt++) {
                    uint32_t af[2][4];
#pragma unroll
                    for (int mt = 0; mt < 2; mt++) {
                        uint32_t r = (uint32_t)(wm * 32 + mt * 16) + a_m;
                        uint32_t c = (uint32_t)(kt * 16) + a_ch;
                        ldsm_x4(af[mt], sa + sw128(r * 128 + c * 2));
                    }
                    uint32_t bf[NT][2];
#pragma unroll
                    for (int nt = 0; nt < NT; nt++) {
                        uint32_t n = (uint32_t)(wn * (NOUT / 2) + nt * 8) + b_nl;
                        uint32_t c = (uint32_t)(kt * 16) + b_ch;
                        ldsm_x2(bf[nt], sb + sw128(n * 128 + c * 2));
                    }
#pragma unroll
                    for (int mt = 0; mt < 2; mt++)
#pragma unroll
                        for (int nt = 0; nt < NT; nt++)
                            mma16816(acc[mt][nt], af[mt], bf[nt]);
                }
            }
        }
    }

    // epilogue: bias (+relu); optional fp32 out; optional hi/lo image
    const int gq = l >> 2;
    const int tq = l & 3;
    char* hb = himg ? himg + (size_t)bid * ABLK : nullptr;
#pragma unroll
    for (int mt = 0; mt < 2; mt++) {
        int rrl = wm * 32 + mt * 16 + gq;
        int r0g = row0 + rrl;
        bool ok0 = r0g < M;
        bool ok8 = (r0g + 8) < M;
#pragma unroll
        for (int nt = 0; nt < NT; nt++) {
            int col = wn * (NOUT / 2) + nt * 8 + tq * 2;
            float b0 = __ldg(&bias[col]);
            float b1 = __ldg(&bias[col + 1]);
            float d0 = acc[mt][nt][0] + b0;
            float d1 = acc[mt][nt][1] + b1;
            float d2 = acc[mt][nt][2] + b0;
            float d3 = acc[mt][nt][3] + b1;
            if (do_relu) {
                d0 = fmaxf(d0, 0.f);
                d1 = fmaxf(d1, 0.f);
                d2 = fmaxf(d2, 0.f);
                d3 = fmaxf(d3, 0.f);
            }
            if (out) {
                if (ok0)
                    *reinterpret_cast<float2*>(out + (size_t)r0g * NOUT + col) =
                        make_float2(d0, d1);
                if (ok8)
                    *reinterpret_cast<float2*>(out + (size_t)(r0g + 8) * NOUT + col) =
                        make_float2(d2, d3);
            }
            if (hb) {
                int chc = col >> 6;
                int kk = col & 63;
                char* hc = hb + chc * 16384;
                if (ok0) {
                    uint32_t o = sw128((uint32_t)(rrl * 128 + kk * 2));
                    __nv_bfloat16 a0 = __float2bfloat16(d0);
                    __nv_bfloat16 a1 = __float2bfloat16(d1);
                    *reinterpret_cast<uint32_t*>(hc + o) = bfpack2(a0, a1);
                    *reinterpret_cast<uint32_t*>(hc + 32768 + o) = bfpack2(
                        __float2bfloat16(d0 - __bfloat162float(a0)),
                        __float2bfloat16(d1 - __bfloat162float(a1)));
                }
                if (ok8) {
                    uint32_t o = sw128((uint32_t)((rrl + 8) * 128 + kk * 2));
                    __nv_bfloat16 a2 = __float2bfloat16(d2);
                    __nv_bfloat16 a3 = __float2bfloat16(d3);
                    *reinterpret_cast<uint32_t*>(hc + o) = bfpack2(a2, a3);
                    *reinterpret_cast<uint32_t*>(hc + 32768 + o) = bfpack2(
                        __float2bfloat16(d2 - __bfloat162float(a2)),
                        __float2bfloat16(d3 - __bfloat162float(a3)));
                }
            }
        }
    }
}

// ---------------- layer-2 quad GEMM: 4 single-operand K=128 segments ---------
struct Seg {
    const char* iA;     // A image (ABLK-strided blocks)
    const char* iW;     // W image
    const float* bias;  // bias (g_zero64 for projections)
    float* out;         // fp32 output [M, 64]
    int M;
};
__global__ void __launch_bounds__(256) sage_gemm2_quad(Seg s0, Seg s1, Seg s2,
                                                       Seg s3, int n0, int n1,
                                                       int n2) {
    constexpr int NOUT = H2;
    constexpr int NT = NOUT / 16;        // 4
    constexpr int A_BYTES = 128 * 128;   // 16KB
    constexpr int B_BYTES = NOUT * 128;  // 8KB
    extern __shared__ char smem[];
    char* A_HI = smem;
    char* A_LO = smem + A_BYTES;
    char* B_HI = smem + 2 * A_BYTES;
    char* B_LO = smem + 2 * A_BYTES + B_BYTES;

    int b = blockIdx.x;
    Seg sg;
    int bid;
    if (b < n0) { sg = s0; bid = b; }
    else if (b < n0 + n1) { sg = s1; bid = b - n0; }
    else if (b < n0 + n1 + n2) { sg = s2; bid = b - n0 - n1; }
    else { sg = s3; bid = b - n0 - n1 - n2; }

    const int tid = threadIdx.x;
    const int w = tid >> 5;
    const int l = tid & 31;
    const int wm = w & 3;
    const int wn = w >> 2;
    const int row0 = bid * 128;

    const uint32_t saAH = smem_u32(A_HI);
    const uint32_t saAL = smem_u32(A_LO);
    const uint32_t saBH = smem_u32(B_HI);
    const uint32_t saBL = smem_u32(B_LO);

    float acc[2][NT][4];
#pragma unroll
    for (int mt = 0; mt < 2; mt++)
#pragma unroll
        for (int nt = 0; nt < NT; nt++)
#pragma unroll
            for (int j = 0; j < 4; j++) acc[mt][nt][j] = 0.f;

    const uint32_t a_m = (uint32_t)(l & 15);
    const uint32_t a_ch = (uint32_t)(l >> 4) * 8;
    const uint32_t b_nl = (uint32_t)(l & 7);
    const uint32_t b_ch = (uint32_t)((l >> 3) & 1) * 8;

    const char* iA = sg.iA + (size_t)bid * ABLK;
    for (int ch = 0; ch < 2; ++ch) {
        __syncthreads();
        {
            const char* aimg = iA + ch * 16384;
#pragma unroll
            for (int j = 0; j < 4; j++) {
                uint32_t o = (uint32_t)(tid * 16 + j * 4096);
                cp_async16(saAH + o, aimg + o);
                cp_async16(saAL + o, aimg + 32768 + o);
            }
        }
        {
            const char* bimg = sg.iW + ch * B_BYTES;
#pragma unroll
            for (int j = 0; j < 2; j++) {
                uint32_t o = (uint32_t)(tid * 16 + j * 4096);
                cp_async16(saBH + o, bimg + o);
                cp_async16(saBL + o, bimg + 2 * B_BYTES + o);
            }
        }
        cp_async_commit();
        cp_async_wait_all();
        __syncthreads();

#pragma unroll
        for (int p = 0; p < 3; p++) {
            const uint32_t sa = (p == 2) ? saAL : saAH;
            const uint32_t sb = (p == 1) ? saBL : saBH;
#pragma unroll
            for (int kt = 0; kt < 4; kt++) {
                uint32_t af[2][4];
#pragma unroll
                for (int mt = 0; mt < 2; mt++) {
                    uint32_t r = (uint32_t)(wm * 32 + mt * 16) + a_m;
                    uint32_t c = (uint32_t)(kt * 16) + a_ch;
                    ldsm_x4(af[mt], sa + sw128(r * 128 + c * 2));
                }
                uint32_t bf[NT][2];
#pragma unroll
                for (int nt = 0; nt < NT; nt++) {
                    uint32_t n = (uint32_t)(wn * (NOUT / 2) + nt * 8) + b_nl;
                    uint32_t c = (uint32_t)(kt * 16) + b_ch;
                    ldsm_x2(bf[nt], sb + sw128(n * 128 + c * 2));
                }
#pragma unroll
                for (int mt = 0; mt < 2; mt++)
#pragma unroll
                    for (int nt = 0; nt < NT; nt++)
                        mma16816(acc[mt][nt], af[mt], bf[nt]);
            }
        }
    }

    const int gq = l >> 2;
    const int tq = l & 3;
#pragma unroll
    for (int mt = 0; mt < 2; mt++) {
        int r0g = row0 + wm * 32 + mt * 16 + gq;
#pragma unroll
        for (int nt = 0; nt < NT; nt++) {
            int col = wn * (NOUT / 2) + nt * 8 + tq * 2;
            float b0 = __ldg(&sg.bias[col]);
            float b1 = __ldg(&sg.bias[col + 1]);
            if (r0g < sg.M)
                *reinterpret_cast<float2*>(sg.out + (size_t)r0g * NOUT + col) =
                    make_float2(acc[mt][nt][0] + b0, acc[mt][nt][1] + b1);
            if (r0g + 8 < sg.M)
                *reinterpret_cast<float2*>(sg.out + (size_t)(r0g + 8) * NOUT + col) =
                    make_float2(acc[mt][nt][2] + b0, acc[mt][nt][3] + b1);
        }
    }
}

// ---------------- host launch -----------------------------------------------
extern "C" void kernel_launch(void* const* d_in, const int* in_sizes, int n_in,
                              void* d_out, int out_size) {
    const float* x_user = (const float*)d_in[0];
    const float* x_song = (const float*)d_in[1];
    const int* us_src = (const int*)d_in[2];
    const int* us_dst = (const int*)d_in[3];
    const int* su_src = (const int*)d_in[4];
    const int* su_dst = (const int*)d_in[5];
    const float* W1_us_n = (const float*)d_in[6];
    const float* W1_us_s = (const float*)d_in[7];
    const float* b1_us = (const float*)d_in[8];
    const float* W1_su_n = (const float*)d_in[9];
    const float* W1_su_s = (const float*)d_in[10];
    const float* b1_su = (const float*)d_in[11];
    const float* W2_us_n = (const float*)d_in[12];
    const float* W2_us_s = (const float*)d_in[13];
    const float* b2_us = (const float*)d_in[14];
    const float* W2_su_n = (const float*)d_in[15];
    const float* W2_su_s = (const float*)d_in[16];
    const float* b2_su = (const float*)d_in[17];
    float* out = (float*)d_out;

    float *p_user, *p_song, *zero64;
    int *cnt_user, *cnt_song, *off_user, *off_song, *fin_user, *fin_song;
    int *cur_user, *cur_song, *srt_us, *srt_su, *part;
    char *wimg, *ximg_s, *ximg_u, *mimg_s, *mimg_u, *himg_s, *himg_u;
    cudaGetSymbolAddress((void**)&p_user, g_p_user);
    cudaGetSymbolAddress((void**)&p_song, g_p_song);
    cudaGetSymbolAddress((void**)&zero64, g_zero64);
    cudaGetSymbolAddress((void**)&cnt_user, g_cnt_user);
    cudaGetSymbolAddress((void**)&cnt_song, g_cnt_song);
    cudaGetSymbolAddress((void**)&off_user, g_off_user);
    cudaGetSymbolAddress((void**)&off_song, g_off_song);
    cudaGetSymbolAddress((void**)&fin_user, g_fin_user);
    cudaGetSymbolAddress((void**)&fin_song, g_fin_song);
    cudaGetSymbolAddress((void**)&cur_user, g_cur_user);
    cudaGetSymbolAddress((void**)&cur_song, g_cur_song);
    cudaGetSymbolAddress((void**)&srt_us, g_srt_us);
    cudaGetSymbolAddress((void**)&srt_su, g_srt_su);
    cudaGetSymbolAddress((void**)&part, g_part);
    cudaGetSymbolAddress((void**)&wimg, g_wimg);
    cudaGetSymbolAddress((void**)&ximg_s, g_ximg_song);
    cudaGetSymbolAddress((void**)&ximg_u, g_ximg_user);
    cudaGetSymbolAddress((void**)&mimg_s, g_mimg_song);
    cudaGetSymbolAddress((void**)&mimg_u, g_mimg_user);
    cudaGetSymbolAddress((void**)&himg_s, g_himg_song);
    cudaGetSymbolAddress((void**)&himg_u, g_himg_user);

    const int NB_S = (NS + 1023) / 1024;  // 49
    const int NB_U = (NU + 1023) / 1024;  // 98

    const int SMEM1 = 2 * 128 * 128 + 2 * H1 * 128;  // 65536 B
    const int SMEM2 = 2 * 128 * 128 + 2 * H2 * 128;  // 49152 B
    cudaFuncSetAttribute(sage_gemm_mma<H1>,
                         cudaFuncAttributeMaxDynamicSharedMemorySize, SMEM1);
    cudaFuncSetAttribute(sage_gemm2_quad,
                         cudaFuncAttributeMaxDynamicSharedMemorySize, SMEM2);

    // ---- W image precompute
    {
        WPtrs wp;
        wp.w[0] = W1_us_s; wp.w[1] = W1_us_n; wp.w[2] = W1_su_s; wp.w[3] = W1_su_n;
        wp.w[4] = W2_us_s; wp.w[5] = W2_us_n; wp.w[6] = W2_su_s; wp.w[7] = W2_su_n;
        dim3 g((128 * H1 + 255) / 256, 8);
        wimg_kernel<<<g, 256>>>(wp, wimg);
    }
    const char* i1_us_s = wimg;
    const char* i1_us_n = wimg + 65536;
    const char* i1_su_s = wimg + 2 * 65536;
    const char* i1_su_n = wimg + 3 * 65536;
    const char* i2_us_s = wimg + 4 * 65536;
    const char* i2_us_n = wimg + 4 * 65536 + 32768;
    const char* i2_su_s = wimg + 4 * 65536 + 2 * 32768;
    const char* i2_su_n = wimg + 4 * 65536 + 3 * 32768;

    // ---- X images (self operand for layer 1)
    ximg_dual<<<(NS + NU + 7) / 8, 256>>>(x_song, ximg_s, NS, x_user, ximg_u, NU);

    // ---- CSR build
    zero_int2<<<(NU + 255) / 256, 256>>>(cnt_user, NU, cnt_song, NS);
    count_kernel<<<(NE + 255) / 256, 256>>>(us_dst, su_dst, cnt_song, cnt_user, NE);
    scan_block_dual<<<NB_S + NB_U, 1024>>>(cnt_song, off_song, NS, cnt_user,
                                           off_user, NU, part, NB_S);
    scan_partials_dual<<<1, 128>>>(part, NB_S, NB_U);
    scan_finish_dual<<<(NS + NU + 255) / 256, 256>>>(
        off_song, fin_song, cur_song, NS, off_user, fin_user, cur_user, NU,
        part, NB_S);
    bin_dual<<<(NE + 255) / 256, 256>>>(us_src, us_dst, su_src, su_dst, cur_song,
                                        cur_user, srt_us, srt_su, NE);

    // ---- layer 1: gather means (of x) into mean images, then GEMM -> himg
    gather_dual<<<(NS + NU + 7) / 8, 256>>>(x_user, srt_us, fin_song, mimg_s, NS,
                                            x_song, srt_su, fin_user, mimg_u, NU);
    sage_gemm_mma<H1><<<NBS + NBU, 256, SMEM1>>>(
        ximg_s, mimg_s, i1_us_s, i1_us_n, b1_us, nullptr, himg_s, NS, NBS,
        ximg_u, mimg_u, i1_su_s, i1_su_n, b1_su, nullptr, himg_u, NU, 1);

    // ---- layer 2: quad GEMM (self song/user -> out, projections -> p)
    {
        Seg s0{himg_s, i2_us_s, b2_us, out + (size_t)NU * H2, NS};  // self song
        Seg s1{himg_u, i2_su_s, b2_su, out, NU};                    // self user
        Seg s2{himg_u, i2_us_n, zero64, p_user, NU};                // proj user
        Seg s3{himg_s, i2_su_n, zero64, p_song, NS};                // proj song
        sage_gemm2_quad<<<NBS + NBU + NBU + NBS, 256, SMEM2>>>(s0, s1, s2, s3,
                                                               NBS, NBU, NBU);
    }
    // ---- gather mean of projections, add into out
    gather_add_dual<<<(NS + NU + 7) / 8, 256>>>(
        p_user, srt_us, fin_song, out + (size_t)NU * H2, NS, p_song, srt_su,
        fin_user, out, NU);
}